// round 9
// baseline (speedup 1.0000x reference)
#include <cuda_runtime.h>
#include <cuda_bf16.h>
#include <cstdint>

#define NN 50000
#define EE 800000

// ---------------- scratch (__device__ globals; no allocs) ----------------
__device__ float g_fsum[NN * 3];
__device__ float g_cnt[NN];
__device__ float g_P1[(size_t)NN * 128];   // h @ We1[0:128,:]
__device__ float g_P2[(size_t)NN * 128];   // h @ We1[128:256,:]
__device__ float g_Q1[(size_t)NN * 128];   // h @ Wn1[0:128,:] + bn1
__device__ float g_m[(size_t)EE * 128];    // per-edge message m
__device__ int   g_hist[NN];
__device__ int   g_rowptr[NN];
__device__ int   g_cursor[NN];
__device__ int   g_perm[EE];

// Weight fragments for mma.sync m16n8k16 (bf16 hi/lo), per-lane order:
//   u32 index = ((hl*16 + nt)*KT + kt)*64 + lane*2 + r
__device__ __align__(16) uint2 g_We1f[16384];  // K=256
__device__ __align__(16) uint2 g_We2f[8192];   // K=128
__device__ __align__(16) uint2 g_Wc1f[8192];   // K=128
__device__ __align__(16) uint2 g_Wn1tf[8192];  // Wn1 top half, K=128
__device__ __align__(16) uint2 g_Wv1f[8192];   // Wv1, K=128

__device__ __forceinline__ float silu_f(float x) {
    return x / (1.0f + __expf(-x));
}

__device__ __forceinline__ void split_pack(float f0, float f1, uint32_t& hi, uint32_t& lo) {
    __nv_bfloat162 bh = __floats2bfloat162_rn(f0, f1);
    float2 bf = __bfloat1622float2(bh);
    __nv_bfloat162 bl = __floats2bfloat162_rn(f0 - bf.x, f1 - bf.y);
    hi = *(uint32_t*)&bh;
    lo = *(uint32_t*)&bl;
}

__device__ __forceinline__ void mma16816(float* c, const uint32_t* a, const uint32_t* b) {
    asm volatile(
        "mma.sync.aligned.m16n8k16.row.col.f32.bf16.bf16.f32 "
        "{%0,%1,%2,%3}, {%4,%5,%6,%7}, {%8,%9}, {%0,%1,%2,%3};"
        : "+f"(c[0]), "+f"(c[1]), "+f"(c[2]), "+f"(c[3])
        : "r"(a[0]), "r"(a[1]), "r"(a[2]), "r"(a[3]), "r"(b[0]), "r"(b[1]));
}

#define SAS 136   // A stride (bf16) for K=128 tiles
#define SMS 132   // fp32 m smem stride (floats), 16B-aligned rows

// ---------------- CSR build kernels --------------------------------------
__global__ void hist_kernel(const int* __restrict__ row) {
    int e = blockIdx.x * blockDim.x + threadIdx.x;
    if (e < EE) atomicAdd(&g_hist[row[e]], 1);
}

__global__ void scan_kernel() {   // single CTA, 1024 threads
    __shared__ int part[1024];
    int tid = threadIdx.x;
    int b0 = tid * 49;
    int b1 = b0 + 49; if (b1 > NN) b1 = NN;
    int s = 0;
    for (int b = b0; b < b1; b++) s += g_hist[b];
    part[tid] = s;
    __syncthreads();
    for (int off = 1; off < 1024; off <<= 1) {
        int v = (tid >= off) ? part[tid - off] : 0;
        __syncthreads();
        part[tid] += v;
        __syncthreads();
    }
    int run = part[tid] - s;   // exclusive prefix
    for (int b = b0; b < b1; b++) {
        g_rowptr[b] = run;
        g_cursor[b] = run;
        g_cnt[b] = (float)g_hist[b];
        run += g_hist[b];
    }
}

__global__ void fill_kernel(const int* __restrict__ row) {
    int e = blockIdx.x * blockDim.x + threadIdx.x;
    if (e < EE) {
        int p = atomicAdd(&g_cursor[row[e]], 1);
        g_perm[p] = e;
    }
}

// ---------------- prep: weights -> bf16 hi/lo fragment order --------------
__global__ void prep_weights_f(const float* __restrict__ We1,
                               const float* __restrict__ We2,
                               const float* __restrict__ Wc1,
                               const float* __restrict__ Wn1,
                               const float* __restrict__ Wv1) {
    int i = blockIdx.x * blockDim.x + threadIdx.x;
    const float* W; uint32_t* out; int KT, j;
    if (i < 32768)      { W = We1; out = (uint32_t*)g_We1f;  KT = 16; j = i; }
    else if (i < 49152) { W = We2; out = (uint32_t*)g_We2f;  KT = 8;  j = i - 32768; }
    else if (i < 65536) { W = Wc1; out = (uint32_t*)g_Wc1f;  KT = 8;  j = i - 49152; }
    else if (i < 81920) { W = Wn1; out = (uint32_t*)g_Wn1tf; KT = 8;  j = i - 65536; }
    else if (i < 98304) { W = Wv1; out = (uint32_t*)g_Wv1f;  KT = 8;  j = i - 81920; }
    else return;
    int per_hl = 16 * KT * 64;
    int hl = j / per_hl; int rem = j % per_hl;
    int nt = rem / (KT * 64); rem %= KT * 64;
    int kt = rem / 64; rem %= 64;
    int lane = rem >> 1, r = rem & 1;
    int g = lane >> 2, tig = lane & 3;
    int n = nt * 8 + g;
    int k = kt * 16 + tig * 2 + r * 8;
    float w0 = W[k * 128 + n], w1 = W[(k + 1) * 128 + n];
    __nv_bfloat162 p;
    if (hl == 0) {
        p.x = __float2bfloat16(w0);
        p.y = __float2bfloat16(w1);
    } else {
        __nv_bfloat16 h0 = __float2bfloat16(w0), h1 = __float2bfloat16(w1);
        p.x = __float2bfloat16(w0 - __bfloat162float(h0));
        p.y = __float2bfloat16(w1 - __bfloat162float(h1));
    }
    out[((hl * 16 + nt) * KT + kt) * 64 + lane * 2 + r] = *(uint32_t*)&p;
}

// ---------------- shared GEMM core: 2x4 mma tiles per warp ----------------
__device__ __forceinline__ void gemm_tiles(
    const unsigned short* __restrict__ sAh, const unsigned short* __restrict__ sAl,
    const uint2* __restrict__ Bf, int KTtot, int kt0, int ktn,
    int wm, int wn, int lane, float acc[2][4][4])
{
    const int g = lane >> 2, tig = lane & 3;
    const int m0 = wm * 32;
    for (int kti = 0; kti < ktn; kti++) {
        uint32_t ah[2][4], al[2][4];
        const int kb = kti * 16 + tig * 2;
#pragma unroll
        for (int mi = 0; mi < 2; mi++) {
            const unsigned short* p0 = sAh + (m0 + mi * 16 + g) * SAS + kb;
            const unsigned short* p1 = p0 + 8 * SAS;
            ah[mi][0] = *(const uint32_t*)p0;
            ah[mi][1] = *(const uint32_t*)p1;
            ah[mi][2] = *(const uint32_t*)(p0 + 8);
            ah[mi][3] = *(const uint32_t*)(p1 + 8);
            const unsigned short* q0 = sAl + (m0 + mi * 16 + g) * SAS + kb;
            const unsigned short* q1 = q0 + 8 * SAS;
            al[mi][0] = *(const uint32_t*)q0;
            al[mi][1] = *(const uint32_t*)q1;
            al[mi][2] = *(const uint32_t*)(q0 + 8);
            al[mi][3] = *(const uint32_t*)(q1 + 8);
        }
        const int kt = kt0 + kti;
#pragma unroll
        for (int ni = 0; ni < 4; ni++) {
            const int nt = wn * 4 + ni;
            uint2 bh = Bf[(nt * KTtot + kt) * 32 + lane];
            uint2 bl = Bf[((16 + nt) * KTtot + kt) * 32 + lane];
            uint32_t bhr[2] = {bh.x, bh.y};
            uint32_t blr[2] = {bl.x, bl.y};
            mma16816(acc[0][ni], ah[0], bhr);
            mma16816(acc[1][ni], ah[1], bhr);
            mma16816(acc[0][ni], al[0], bhr);
            mma16816(acc[1][ni], al[1], bhr);
            mma16816(acc[0][ni], ah[0], blr);
            mma16816(acc[1][ni], ah[1], blr);
        }
    }
}

// ---------------- precompute: P1, P2, Q1, vel — all h-only GEMMs ----------
__global__ __launch_bounds__(256, 2) void precompute_p(
    const float* __restrict__ h,
    const float* __restrict__ bn1,
    const float* __restrict__ bv1,
    const float* __restrict__ Wv2, const float* __restrict__ bv2,
    float* __restrict__ out)
{
    extern __shared__ __align__(16) char smem[];
    unsigned short* sAh = (unsigned short*)smem;
    unsigned short* sAl = (unsigned short*)(smem + 17408);
    float* sBn1 = (float*)(smem + 34816);
    float* sBv1 = (float*)(smem + 35328);
    float* sWv2 = (float*)(smem + 35840);
    float* sVel = (float*)(smem + 36352);

    const int t    = threadIdx.x;
    const int lane = t & 31;
    const int wid  = t >> 5;
    const int wm   = wid >> 2;
    const int wn   = wid & 3;
    const int g    = lane >> 2;
    const int tig  = lane & 3;
    const int n0   = blockIdx.x * 64;

    if (t < 128) {
        sBn1[t] = bn1[t];
        sBv1[t] = bv1[t];
        sWv2[t] = Wv2[t];
    }
    if (t < 64) sVel[t] = 0.0f;

    for (int i = t; i < 64 * 32; i += 256) {
        int e = i >> 5;
        int k = (i & 31) * 4;
        int n = n0 + e;
        float4 v = make_float4(0.f, 0.f, 0.f, 0.f);
        if (n < NN) v = *(const float4*)(h + (size_t)n * 128 + k);
        uint32_t h0, l0, h1, l1;
        split_pack(v.x, v.y, h0, l0);
        split_pack(v.z, v.w, h1, l1);
        *(uint2*)(sAh + e * SAS + k) = make_uint2(h0, h1);
        *(uint2*)(sAl + e * SAS + k) = make_uint2(l0, l1);
    }
    __syncthreads();

    float acc[2][4][4];

    // ---- P1, P2 (We1 halves) ----
#pragma unroll
    for (int p = 0; p < 2; p++) {
#pragma unroll
        for (int a = 0; a < 2; a++)
#pragma unroll
            for (int b = 0; b < 4; b++)
#pragma unroll
                for (int c = 0; c < 4; c++) acc[a][b][c] = 0.0f;
        gemm_tiles(sAh, sAl, g_We1f, 16, p * 8, 8, wm, wn, lane, acc);
        float* outp = p ? g_P2 : g_P1;
#pragma unroll
        for (int mi = 0; mi < 2; mi++) {
            int rA = n0 + wm * 32 + mi * 16 + g;
            int rB = rA + 8;
#pragma unroll
            for (int ni = 0; ni < 4; ni++) {
                int cb = wn * 32 + ni * 8 + tig * 2;
                if (rA < NN) {
                    outp[(size_t)rA * 128 + cb]     = acc[mi][ni][0];
                    outp[(size_t)rA * 128 + cb + 1] = acc[mi][ni][1];
                }
                if (rB < NN) {
                    outp[(size_t)rB * 128 + cb]     = acc[mi][ni][2];
                    outp[(size_t)rB * 128 + cb + 1] = acc[mi][ni][3];
                }
            }
        }
    }

    // ---- Q1 = h @ Wn1_top + bn1 ----
    {
#pragma unroll
        for (int a = 0; a < 2; a++)
#pragma unroll
            for (int b = 0; b < 4; b++)
#pragma unroll
                for (int c = 0; c < 4; c++) acc[a][b][c] = 0.0f;
        gemm_tiles(sAh, sAl, g_Wn1tf, 8, 0, 8, wm, wn, lane, acc);
#pragma unroll
        for (int mi = 0; mi < 2; mi++) {
            int rA = n0 + wm * 32 + mi * 16 + g;
            int rB = rA + 8;
#pragma unroll
            for (int ni = 0; ni < 4; ni++) {
                int cb = wn * 32 + ni * 8 + tig * 2;
                float b0 = sBn1[cb], b1 = sBn1[cb + 1];
                if (rA < NN) {
                    g_Q1[(size_t)rA * 128 + cb]     = acc[mi][ni][0] + b0;
                    g_Q1[(size_t)rA * 128 + cb + 1] = acc[mi][ni][1] + b1;
                }
                if (rB < NN) {
                    g_Q1[(size_t)rB * 128 + cb]     = acc[mi][ni][2] + b0;
                    g_Q1[(size_t)rB * 128 + cb + 1] = acc[mi][ni][3] + b1;
                }
            }
        }
    }

    // ---- vel = silu(h @ Wv1 + bv1) @ Wv2 + bv2 -> out[0..NN) ----
    {
#pragma unroll
        for (int a = 0; a < 2; a++)
#pragma unroll
            for (int b = 0; b < 4; b++)
#pragma unroll
                for (int c = 0; c < 4; c++) acc[a][b][c] = 0.0f;
        gemm_tiles(sAh, sAl, g_Wv1f, 8, 0, 8, wm, wn, lane, acc);
        float p[4] = {0.f, 0.f, 0.f, 0.f};
#pragma unroll
        for (int ni = 0; ni < 4; ni++) {
            int cb = wn * 32 + ni * 8 + tig * 2;
            float b0 = sBv1[cb], b1 = sBv1[cb + 1];
            float w0 = sWv2[cb], w1 = sWv2[cb + 1];
#pragma unroll
            for (int mi = 0; mi < 2; mi++) {
                p[mi * 2 + 0] += silu_f(acc[mi][ni][0] + b0) * w0
                               + silu_f(acc[mi][ni][1] + b1) * w1;
                p[mi * 2 + 1] += silu_f(acc[mi][ni][2] + b0) * w0
                               + silu_f(acc[mi][ni][3] + b1) * w1;
            }
        }
#pragma unroll
        for (int j = 0; j < 4; j++) {
            p[j] += __shfl_xor_sync(0xffffffffu, p[j], 1);
            p[j] += __shfl_xor_sync(0xffffffffu, p[j], 2);
        }
        __syncthreads();
        if (tig == 0) {
#pragma unroll
            for (int j = 0; j < 4; j++) {
                int rr = wm * 32 + (j >> 1) * 16 + (j & 1) * 8 + g;
                atomicAdd(&sVel[rr], p[j]);
            }
        }
        __syncthreads();
        if (t < 64) {
            int n = n0 + t;
            if (n < NN) out[n] = sVel[t] + bv2[0];
        }
    }
}

// ---------------- edge kernel: 64 edges/CTA, GEMM2+GEMM3 ------------------
#define OFF_AH 0u
#define OFF_AL 17408u
#define OFF_M  34816u      // 64*132*4 = 33792
#define OFF_X  68608u
#define SMEM_EDGE_TOTAL 72960

__global__ __launch_bounds__(256, 2) void edge_kernel_mma(
    const float* __restrict__ coord_diff,
    const int* __restrict__ row, const int* __restrict__ col,
    const float* __restrict__ We1, const float* __restrict__ be1,
    const float* __restrict__ be2,
    const float* __restrict__ bc1, const float* __restrict__ Wc2)
{
    extern __shared__ __align__(16) char smem[];
    unsigned short* sAh = (unsigned short*)(smem + OFF_AH);
    unsigned short* sAl = (unsigned short*)(smem + OFF_AL);
    float* sM    = (float*)(smem + OFF_M);
    int*   sRow  = (int*)  (smem + OFF_X);
    int*   sCol  = (int*)  (smem + OFF_X + 256);
    float* sRad  = (float*)(smem + OFF_X + 512);
    float* sCD   = (float*)(smem + OFF_X + 768);
    float* sBe1  = (float*)(smem + OFF_X + 1536);
    float* sW256 = (float*)(smem + OFF_X + 2048);
    float* sBe2  = (float*)(smem + OFF_X + 2560);
    float* sBc1  = (float*)(smem + OFF_X + 3072);
    float* sWc2  = (float*)(smem + OFF_X + 3584);
    float* sCoef = (float*)(smem + OFF_X + 4096);

    const int t    = threadIdx.x;
    const int lane = t & 31;
    const int wid  = t >> 5;
    const int wm   = wid >> 2;
    const int wn   = wid & 3;
    const int g    = lane >> 2;
    const int tig  = lane & 3;
    const int e0   = blockIdx.x * 64;

    if (t < 64) {
        int e = e0 + t;
        sRow[t] = row[e];
        sCol[t] = col[e];
        float cx = coord_diff[e * 3 + 0];
        float cy = coord_diff[e * 3 + 1];
        float cz = coord_diff[e * 3 + 2];
        sCD[t * 3 + 0] = cx; sCD[t * 3 + 1] = cy; sCD[t * 3 + 2] = cz;
        sRad[t] = cx * cx + cy * cy + cz * cz;
        sCoef[t] = 0.0f;
    }
    if (t < 128) {
        sBe1[t]  = be1[t];
        sW256[t] = We1[256 * 128 + t];
        sBe2[t]  = be2[t];
        sBc1[t]  = bc1[t];
        sWc2[t]  = Wc2[t];
    }
    __syncthreads();

    // ---- h1 = silu(P1[row] + P2[col] + rad*w256 + be1) -> A (K=128) ----
    for (int i = t; i < 64 * 32; i += 256) {
        int e = i >> 5;
        int k = (i & 31) * 4;
        float rad = sRad[e];
        float4 a = *(const float4*)(g_P1 + (size_t)sRow[e] * 128 + k);
        float4 b = *(const float4*)(g_P2 + (size_t)sCol[e] * 128 + k);
        float4 w = *(const float4*)(sW256 + k);
        float4 bb = *(const float4*)(sBe1 + k);
        float x0 = silu_f(a.x + b.x + rad * w.x + bb.x);
        float x1 = silu_f(a.y + b.y + rad * w.y + bb.y);
        float x2 = silu_f(a.z + b.z + rad * w.z + bb.z);
        float x3 = silu_f(a.w + b.w + rad * w.w + bb.w);
        uint32_t h0, l0, h1, l1;
        split_pack(x0, x1, h0, l0);
        split_pack(x2, x3, h1, l1);
        *(uint2*)(sAh + e * SAS + k) = make_uint2(h0, h1);
        *(uint2*)(sAl + e * SAS + k) = make_uint2(l0, l1);
    }
    __syncthreads();

    float acc[2][4][4];

    // ---- GEMM2: m = silu(h1 @ We2 + be2), K=128 ----
#pragma unroll
    for (int a = 0; a < 2; a++)
#pragma unroll
        for (int b = 0; b < 4; b++)
#pragma unroll
            for (int c = 0; c < 4; c++) acc[a][b][c] = 0.0f;
    gemm_tiles(sAh, sAl, g_We2f, 8, 0, 8, wm, wn, lane, acc);
    __syncthreads();

#pragma unroll
    for (int mi = 0; mi < 2; mi++) {
        int rA = wm * 32 + mi * 16 + g;
        int rB = rA + 8;
#pragma unroll
        for (int ni = 0; ni < 4; ni++) {
            int cb = wn * 32 + ni * 8 + tig * 2;
            float b0 = sBe2[cb], b1 = sBe2[cb + 1];
            float m0 = silu_f(acc[mi][ni][0] + b0);
            float m1 = silu_f(acc[mi][ni][1] + b1);
            float m2 = silu_f(acc[mi][ni][2] + b0);
            float m3 = silu_f(acc[mi][ni][3] + b1);
            sM[rA * SMS + cb] = m0;  sM[rA * SMS + cb + 1] = m1;
            sM[rB * SMS + cb] = m2;  sM[rB * SMS + cb + 1] = m3;
            uint32_t hi, lo;
            split_pack(m0, m1, hi, lo);
            *(uint32_t*)(sAh + rA * SAS + cb) = hi;
            *(uint32_t*)(sAl + rA * SAS + cb) = lo;
            split_pack(m2, m3, hi, lo);
            *(uint32_t*)(sAh + rB * SAS + cb) = hi;
            *(uint32_t*)(sAl + rB * SAS + cb) = lo;
        }
    }
    __syncthreads();

    // ---- stream m out (coalesced 16B/lane STG; replaces the RED scatter) ----
    for (int i = t; i < 64 * 32; i += 256) {
        int e = i >> 5;
        int d4 = (i & 31) * 4;
        float4 v = *(const float4*)(sM + e * SMS + d4);
        *(float4*)(g_m + (size_t)(e0 + e) * 128 + d4) = v;
    }

    // ---- GEMM3: K=128 ----
#pragma unroll
    for (int a = 0; a < 2; a++)
#pragma unroll
        for (int b = 0; b < 4; b++)
#pragma unroll
            for (int c = 0; c < 4; c++) acc[a][b][c] = 0.0f;
    gemm_tiles(sAh, sAl, g_Wc1f, 8, 0, 8, wm, wn, lane, acc);

    // ---- epilogue3: coef = sum_n silu(D + bc1) * Wc2 ----
    {
        float p[4] = {0.f, 0.f, 0.f, 0.f};
#pragma unroll
        for (int ni = 0; ni < 4; ni++) {
            int cb = wn * 32 + ni * 8 + tig * 2;
            float b0 = sBc1[cb], b1 = sBc1[cb + 1];
            float w0 = sWc2[cb], w1 = sWc2[cb + 1];
#pragma unroll
            for (int mi = 0; mi < 2; mi++) {
                p[mi * 2 + 0] += silu_f(acc[mi][ni][0] + b0) * w0
                               + silu_f(acc[mi][ni][1] + b1) * w1;
                p[mi * 2 + 1] += silu_f(acc[mi][ni][2] + b0) * w0
                               + silu_f(acc[mi][ni][3] + b1) * w1;
            }
        }
#pragma unroll
        for (int j = 0; j < 4; j++) {
            p[j] += __shfl_xor_sync(0xffffffffu, p[j], 1);
            p[j] += __shfl_xor_sync(0xffffffffu, p[j], 2);
        }
        if (tig == 0) {
#pragma unroll
            for (int j = 0; j < 4; j++) {
                int rr = wm * 32 + (j >> 1) * 16 + (j & 1) * 8 + g;
                atomicAdd(&sCoef[rr], p[j]);
            }
        }
    }
    __syncthreads();

    // ---- force scatter (small; stays atomic) ----
    if (t < 64) {
        int r = sRow[t];
        float c = sCoef[t];
#pragma unroll
        for (int q = 0; q < 3; q++) {
            float v = sCD[t * 3 + q] * c;
            v = fminf(fmaxf(v, -100.0f), 100.0f);
            atomicAdd(&g_fsum[r * 3 + q], v);
        }
    }
}

// ---------------------------------------------------------------------------
// Node kernel: agg = CSR-gather(g_m) ; h_out = silu(Q1 + agg@Wn1_bot)@Wn2+bn2
// out layout: [vel (N)] [force (N*3)] [h_out (N*128)]
// ---------------------------------------------------------------------------
__global__ __launch_bounds__(256, 3) void node_kernel(
    const float* __restrict__ Wn1, const float* __restrict__ Wn2,
    const float* __restrict__ bn2,
    float* __restrict__ out)
{
    extern __shared__ float sm[];
    float* sB = sm;              // [32][128] = 4096
    float* sH = sB + 4096;       // [64][132] = 8448 (agg, then h1 in place)

    const int t    = threadIdx.x;
    const int lane = t & 31;
    const int warp = t >> 5;
    const int col0 = lane * 4;
    const int row0 = warp * 8;
    const int n0   = blockIdx.x * 64;

    // ---- CSR gather: agg rows -> sH (one warp handles one node per iter) ----
    for (int i = t; i < 64 * 32; i += 256) {
        int e  = i >> 5;
        int d4 = (i & 31) * 4;
        int n  = n0 + e;
        float4 s = make_float4(0.f, 0.f, 0.f, 0.f);
        if (n < NN) {
            int beg = g_rowptr[n];
            int len = g_hist[n];
            for (int j = 0; j < len; j++) {
                int eid = g_perm[beg + j];
                float4 mv = *(const float4*)(g_m + (size_t)eid * 128 + d4);
                s.x += mv.x; s.y += mv.y; s.z += mv.z; s.w += mv.w;
            }
        }
        *(float4*)(sH + e * 132 + d4) = s;
    }
    __syncthreads();

    float acc[8][4];

    // ---- GEMM1: acc = Q1 + agg @ Wn1_bot (K=128), A read from sH ----
#pragma unroll
    for (int i = 0; i < 8; i++) {
        int n = n0 + row0 + i;
        if (n < NN) {
            float4 q = *(const float4*)(g_Q1 + (size_t)n * 128 + col0);
            acc[i][0] = q.x; acc[i][1] = q.y; acc[i][2] = q.z; acc[i][3] = q.w;
        } else {
            acc[i][0] = acc[i][1] = acc[i][2] = acc[i][3] = 0.0f;
        }
    }

    for (int kc = 0; kc < 4; kc++) {
        __syncthreads();
        const float4* Wsrc = (const float4*)(Wn1 + (128 + kc * 32) * 128);
        float4* Bdst = (float4*)sB;
        Bdst[t]       = Wsrc[t];
        Bdst[t + 256] = Wsrc[t + 256];
        Bdst[t + 512] = Wsrc[t + 512];
        Bdst[t + 768] = Wsrc[t + 768];
        __syncthreads();
#pragma unroll
        for (int kk = 0; kk < 32; kk++) {
            float4 bv = *(const float4*)(sB + kk * 128 + col0);
            int kg = kc * 32 + kk;
#pragma unroll
            for (int i = 0; i < 8; i++) {
                float a = sH[(row0 + i) * 132 + kg];
                acc[i][0] += a * bv.x;
                acc[i][1] += a * bv.y;
                acc[i][2] += a * bv.z;
                acc[i][3] += a * bv.w;
            }
        }
    }
    __syncthreads();   // all GEMM1 reads of sH complete before in-place write
#pragma unroll
    for (int i = 0; i < 8; i++) {
        float4 v;
        v.x = silu_f(acc[i][0]); v.y = silu_f(acc[i][1]);
        v.z = silu_f(acc[i][2]); v.w = silu_f(acc[i][3]);
        *(float4*)(sH + (row0 + i) * 132 + col0) = v;
    }

    // ---- GEMM2: h_out = sH @ Wn2 + bn2 ----
#pragma unroll
    for (int i = 0; i < 8; i++)
#pragma unroll
        for (int j = 0; j < 4; j++) acc[i][j] = bn2[col0 + j];

    for (int kc = 0; kc < 4; kc++) {
        __syncthreads();
        const float4* Wsrc = (const float4*)(Wn2 + kc * 32 * 128);
        float4* Bdst = (float4*)sB;
        Bdst[t]       = Wsrc[t];
        Bdst[t + 256] = Wsrc[t + 256];
        Bdst[t + 512] = Wsrc[t + 512];
        Bdst[t + 768] = Wsrc[t + 768];
        __syncthreads();
#pragma unroll
        for (int kk = 0; kk < 32; kk++) {
            float4 bv = *(const float4*)(sB + kk * 128 + col0);
            int kg = kc * 32 + kk;
#pragma unroll
            for (int i = 0; i < 8; i++) {
                float a = sH[(row0 + i) * 132 + kg];
                acc[i][0] += a * bv.x;
                acc[i][1] += a * bv.y;
                acc[i][2] += a * bv.z;
                acc[i][3] += a * bv.w;
            }
        }
    }
    {
        float* outH = out + (size_t)4 * NN;
#pragma unroll
        for (int i = 0; i < 8; i++) {
            int n = n0 + row0 + i;
            if (n < NN) {
                float4 v;
                v.x = acc[i][0]; v.y = acc[i][1]; v.z = acc[i][2]; v.w = acc[i][3];
                *(float4*)(outH + (size_t)n * 128 + col0) = v;
            }
        }
    }

    // ---- force normalize (cnt from histogram) ----
    if (t < 64) {
        int n = n0 + t;
        if (n < NN) {
            float c = g_cnt[n];
            float inv = 1.0f / fmaxf(c, 1.0f);
            out[NN + (size_t)n * 3 + 0] = g_fsum[n * 3 + 0] * inv;
            out[NN + (size_t)n * 3 + 1] = g_fsum[n * 3 + 1] * inv;
            out[NN + (size_t)n * 3 + 2] = g_fsum[n * 3 + 2] * inv;
        }
    }
}

// ---------------------------------------------------------------------------
extern "C" void kernel_launch(void* const* d_in, const int* in_sizes, int n_in,
                              void* d_out, int out_size)
{
    const float* h          = (const float*)d_in[0];
    const float* coord_diff = (const float*)d_in[1];
    const int*   row        = (const int*)  d_in[2];
    const int*   col        = (const int*)  d_in[3];
    const float* We1 = (const float*)d_in[4];
    const float* be1 = (const float*)d_in[5];
    const float* We2 = (const float*)d_in[6];
    const float* be2 = (const float*)d_in[7];
    const float* Wn1 = (const float*)d_in[8];
    const float* bn1 = (const float*)d_in[9];
    const float* Wn2 = (const float*)d_in[10];
    const float* bn2 = (const float*)d_in[11];
    const float* Wc1 = (const float*)d_in[12];
    const float* bc1 = (const float*)d_in[13];
    const float* Wc2 = (const float*)d_in[14];
    const float* Wv1 = (const float*)d_in[15];
    const float* bv1 = (const float*)d_in[16];
    const float* Wv2 = (const float*)d_in[17];
    const float* bv2 = (const float*)d_in[18];
    float* out = (float*)d_out;

    void *fsump, *histp;
    cudaGetSymbolAddress(&fsump, g_fsum);
    cudaGetSymbolAddress(&histp, g_hist);
    cudaMemsetAsync(fsump, 0, (size_t)NN * 3 * sizeof(float));
    cudaMemsetAsync(histp, 0, (size_t)NN * sizeof(int));

    prep_weights_f<<<384, 256>>>(We1, We2, Wc1, Wn1, Wv1);
    hist_kernel<<<(EE + 255) / 256, 256>>>(row);
    scan_kernel<<<1, 1024>>>();
    fill_kernel<<<(EE + 255) / 256, 256>>>(row);

    precompute_p<<<(NN + 63) / 64, 256, 36864>>>(h, bn1, bv1, Wv2, bv2, out);

    cudaFuncSetAttribute(edge_kernel_mma, cudaFuncAttributeMaxDynamicSharedMemorySize,
                         SMEM_EDGE_TOTAL);
    edge_kernel_mma<<<EE / 64, 256, SMEM_EDGE_TOTAL>>>(
        coord_diff, row, col, We1, be1, be2, bc1, Wc2);

    const size_t smN = (size_t)(4096 + 8448) * sizeof(float);
    cudaFuncSetAttribute(node_kernel, cudaFuncAttributeMaxDynamicSharedMemorySize, (int)smN);
    node_kernel<<<(NN + 63) / 64, 256, smN>>>(Wn1, Wn2, bn2, out);
}

// round 11
// speedup vs baseline: 1.0269x; 1.0269x over previous
#include <cuda_runtime.h>
#include <cuda_bf16.h>
#include <cstdint>

#define NN 50000
#define EE 800000

// ---------------- scratch (__device__ globals; no allocs) ----------------
__device__ float g_agg[(size_t)NN * 128];
__device__ float g_fsum[NN * 3];
__device__ float g_cnt[NN];
__device__ float g_P1[(size_t)NN * 128];   // h @ We1[0:128,:]
__device__ float g_P2[(size_t)NN * 128];   // h @ We1[128:256,:]
__device__ float g_Q1[(size_t)NN * 128];   // h @ Wn1[0:128,:] + bn1
__device__ int   g_hist[NN];
__device__ int   g_cursor[NN];
__device__ int   g_perm[EE];

// Weight fragments for mma.sync m16n8k16 (bf16 hi/lo), per-lane order:
//   u32 index = ((hl*16 + nt)*KT + kt)*64 + lane*2 + r
__device__ __align__(16) uint2 g_We1f[16384];  // K=256
__device__ __align__(16) uint2 g_We2f[8192];   // K=128
__device__ __align__(16) uint2 g_Wc1f[8192];   // K=128
__device__ __align__(16) uint2 g_Wn1tf[8192];  // Wn1 top half, K=128
__device__ __align__(16) uint2 g_Wv1f[8192];   // Wv1, K=128

__device__ __forceinline__ float silu_f(float x) {
    return x / (1.0f + __expf(-x));
}

__device__ __forceinline__ void split_pack(float f0, float f1, uint32_t& hi, uint32_t& lo) {
    __nv_bfloat162 bh = __floats2bfloat162_rn(f0, f1);
    float2 bf = __bfloat1622float2(bh);
    __nv_bfloat162 bl = __floats2bfloat162_rn(f0 - bf.x, f1 - bf.y);
    hi = *(uint32_t*)&bh;
    lo = *(uint32_t*)&bl;
}

__device__ __forceinline__ void mma16816(float* c, const uint32_t* a, const uint32_t* b) {
    asm volatile(
        "mma.sync.aligned.m16n8k16.row.col.f32.bf16.bf16.f32 "
        "{%0,%1,%2,%3}, {%4,%5,%6,%7}, {%8,%9}, {%0,%1,%2,%3};"
        : "+f"(c[0]), "+f"(c[1]), "+f"(c[2]), "+f"(c[3])
        : "r"(a[0]), "r"(a[1]), "r"(a[2]), "r"(a[3]), "r"(b[0]), "r"(b[1]));
}

__device__ __forceinline__ void red_add_v4(float* gptr, float4 v) {
    asm volatile("red.global.add.v4.f32 [%0], {%1, %2, %3, %4};"
                 :: "l"(gptr), "f"(v.x), "f"(v.y), "f"(v.z), "f"(v.w) : "memory");
}

#define SAS 136   // A stride (bf16) for K=128 tiles
#define SMS 132   // fp32 m smem stride (floats), 16B-aligned rows

// ---------------- CSR build: sort edges by row ----------------------------
__global__ void hist_kernel(const int* __restrict__ row) {
    int e = blockIdx.x * blockDim.x + threadIdx.x;
    if (e < EE) atomicAdd(&g_hist[row[e]], 1);
}

__global__ void scan_kernel() {   // single CTA, 1024 threads
    __shared__ int part[1024];
    int tid = threadIdx.x;
    int b0 = tid * 49;
    int b1 = b0 + 49; if (b1 > NN) b1 = NN;
    int s = 0;
    for (int b = b0; b < b1; b++) s += g_hist[b];
    part[tid] = s;
    __syncthreads();
    for (int off = 1; off < 1024; off <<= 1) {
        int v = (tid >= off) ? part[tid - off] : 0;
        __syncthreads();
        part[tid] += v;
        __syncthreads();
    }
    int run = part[tid] - s;   // exclusive prefix
    for (int b = b0; b < b1; b++) {
        g_cursor[b] = run;
        g_cnt[b] = (float)g_hist[b];
        run += g_hist[b];
    }
}

__global__ void fill_kernel(const int* __restrict__ row) {
    int e = blockIdx.x * blockDim.x + threadIdx.x;
    if (e < EE) {
        int p = atomicAdd(&g_cursor[row[e]], 1);
        g_perm[p] = e;
    }
}

// ---------------- prep: weights -> bf16 hi/lo fragment order --------------
__global__ void prep_weights_f(const float* __restrict__ We1,
                               const float* __restrict__ We2,
                               const float* __restrict__ Wc1,
                               const float* __restrict__ Wn1,
                               const float* __restrict__ Wv1) {
    int i = blockIdx.x * blockDim.x + threadIdx.x;
    const float* W; uint32_t* out; int KT, j;
    if (i < 32768)      { W = We1; out = (uint32_t*)g_We1f;  KT = 16; j = i; }
    else if (i < 49152) { W = We2; out = (uint32_t*)g_We2f;  KT = 8;  j = i - 32768; }
    else if (i < 65536) { W = Wc1; out = (uint32_t*)g_Wc1f;  KT = 8;  j = i - 49152; }
    else if (i < 81920) { W = Wn1; out = (uint32_t*)g_Wn1tf; KT = 8;  j = i - 65536; }
    else if (i < 98304) { W = Wv1; out = (uint32_t*)g_Wv1f;  KT = 8;  j = i - 81920; }
    else return;
    int per_hl = 16 * KT * 64;
    int hl = j / per_hl; int rem = j % per_hl;
    int nt = rem / (KT * 64); rem %= KT * 64;
    int kt = rem / 64; rem %= 64;
    int lane = rem >> 1, r = rem & 1;
    int g = lane >> 2, tig = lane & 3;
    int n = nt * 8 + g;
    int k = kt * 16 + tig * 2 + r * 8;
    float w0 = W[k * 128 + n], w1 = W[(k + 1) * 128 + n];
    __nv_bfloat162 p;
    if (hl == 0) {
        p.x = __float2bfloat16(w0);
        p.y = __float2bfloat16(w1);
    } else {
        __nv_bfloat16 h0 = __float2bfloat16(w0), h1 = __float2bfloat16(w1);
        p.x = __float2bfloat16(w0 - __bfloat162float(h0));
        p.y = __float2bfloat16(w1 - __bfloat162float(h1));
    }
    out[((hl * 16 + nt) * KT + kt) * 64 + lane * 2 + r] = *(uint32_t*)&p;
}

// ---------------- shared GEMM core: 2x4 mma tiles per warp ----------------
__device__ __forceinline__ void gemm_tiles(
    const unsigned short* __restrict__ sAh, const unsigned short* __restrict__ sAl,
    const uint2* __restrict__ Bf, int KTtot, int kt0, int ktn,
    int wm, int wn, int lane, float acc[2][4][4])
{
    const int g = lane >> 2, tig = lane & 3;
    const int m0 = wm * 32;
    for (int kti = 0; kti < ktn; kti++) {
        uint32_t ah[2][4], al[2][4];
        const int kb = kti * 16 + tig * 2;
#pragma unroll
        for (int mi = 0; mi < 2; mi++) {
            const unsigned short* p0 = sAh + (m0 + mi * 16 + g) * SAS + kb;
            const unsigned short* p1 = p0 + 8 * SAS;
            ah[mi][0] = *(const uint32_t*)p0;
            ah[mi][1] = *(const uint32_t*)p1;
            ah[mi][2] = *(const uint32_t*)(p0 + 8);
            ah[mi][3] = *(const uint32_t*)(p1 + 8);
            const unsigned short* q0 = sAl + (m0 + mi * 16 + g) * SAS + kb;
            const unsigned short* q1 = q0 + 8 * SAS;
            al[mi][0] = *(const uint32_t*)q0;
            al[mi][1] = *(const uint32_t*)q1;
            al[mi][2] = *(const uint32_t*)(q0 + 8);
            al[mi][3] = *(const uint32_t*)(q1 + 8);
        }
        const int kt = kt0 + kti;
#pragma unroll
        for (int ni = 0; ni < 4; ni++) {
            const int nt = wn * 4 + ni;
            uint2 bh = Bf[(nt * KTtot + kt) * 32 + lane];
            uint2 bl = Bf[((16 + nt) * KTtot + kt) * 32 + lane];
            uint32_t bhr[2] = {bh.x, bh.y};
            uint32_t blr[2] = {bl.x, bl.y};
            mma16816(acc[0][ni], ah[0], bhr);
            mma16816(acc[1][ni], ah[1], bhr);
            mma16816(acc[0][ni], al[0], bhr);
            mma16816(acc[1][ni], al[1], bhr);
            mma16816(acc[0][ni], ah[0], blr);
            mma16816(acc[1][ni], ah[1], blr);
        }
    }
}

// ---------------- precompute: P1, P2, Q1, vel — all h-only GEMMs ----------
__global__ __launch_bounds__(256, 2) void precompute_p(
    const float* __restrict__ h,
    const float* __restrict__ bn1,
    const float* __restrict__ bv1,
    const float* __restrict__ Wv2, const float* __restrict__ bv2,
    float* __restrict__ out)
{
    extern __shared__ __align__(16) char smem[];
    unsigned short* sAh = (unsigned short*)smem;
    unsigned short* sAl = (unsigned short*)(smem + 17408);
    float* sBn1 = (float*)(smem + 34816);
    float* sBv1 = (float*)(smem + 35328);
    float* sWv2 = (float*)(smem + 35840);
    float* sVel = (float*)(smem + 36352);

    const int t    = threadIdx.x;
    const int lane = t & 31;
    const int wid  = t >> 5;
    const int wm   = wid >> 2;
    const int wn   = wid & 3;
    const int g    = lane >> 2;
    const int tig  = lane & 3;
    const int n0   = blockIdx.x * 64;

    if (t < 128) {
        sBn1[t] = bn1[t];
        sBv1[t] = bv1[t];
        sWv2[t] = Wv2[t];
    }
    if (t < 64) sVel[t] = 0.0f;

    for (int i = t; i < 64 * 32; i += 256) {
        int e = i >> 5;
        int k = (i & 31) * 4;
        int n = n0 + e;
        float4 v = make_float4(0.f, 0.f, 0.f, 0.f);
        if (n < NN) v = *(const float4*)(h + (size_t)n * 128 + k);
        uint32_t h0, l0, h1, l1;
        split_pack(v.x, v.y, h0, l0);
        split_pack(v.z, v.w, h1, l1);
        *(uint2*)(sAh + e * SAS + k) = make_uint2(h0, h1);
        *(uint2*)(sAl + e * SAS + k) = make_uint2(l0, l1);
    }
    __syncthreads();

    float acc[2][4][4];

    // ---- P1, P2 (We1 halves) ----
#pragma unroll
    for (int p = 0; p < 2; p++) {
#pragma unroll
        for (int a = 0; a < 2; a++)
#pragma unroll
            for (int b = 0; b < 4; b++)
#pragma unroll
                for (int c = 0; c < 4; c++) acc[a][b][c] = 0.0f;
        gemm_tiles(sAh, sAl, g_We1f, 16, p * 8, 8, wm, wn, lane, acc);
        float* outp = p ? g_P2 : g_P1;
#pragma unroll
        for (int mi = 0; mi < 2; mi++) {
            int rA = n0 + wm * 32 + mi * 16 + g;
            int rB = rA + 8;
#pragma unroll
            for (int ni = 0; ni < 4; ni++) {
                int cb = wn * 32 + ni * 8 + tig * 2;
                if (rA < NN) {
                    outp[(size_t)rA * 128 + cb]     = acc[mi][ni][0];
                    outp[(size_t)rA * 128 + cb + 1] = acc[mi][ni][1];
                }
                if (rB < NN) {
                    outp[(size_t)rB * 128 + cb]     = acc[mi][ni][2];
                    outp[(size_t)rB * 128 + cb + 1] = acc[mi][ni][3];
                }
            }
        }
    }

    // ---- Q1 = h @ Wn1_top + bn1 ----
    {
#pragma unroll
        for (int a = 0; a < 2; a++)
#pragma unroll
            for (int b = 0; b < 4; b++)
#pragma unroll
                for (int c = 0; c < 4; c++) acc[a][b][c] = 0.0f;
        gemm_tiles(sAh, sAl, g_Wn1tf, 8, 0, 8, wm, wn, lane, acc);
#pragma unroll
        for (int mi = 0; mi < 2; mi++) {
            int rA = n0 + wm * 32 + mi * 16 + g;
            int rB = rA + 8;
#pragma unroll
            for (int ni = 0; ni < 4; ni++) {
                int cb = wn * 32 + ni * 8 + tig * 2;
                float b0 = sBn1[cb], b1 = sBn1[cb + 1];
                if (rA < NN) {
                    g_Q1[(size_t)rA * 128 + cb]     = acc[mi][ni][0] + b0;
                    g_Q1[(size_t)rA * 128 + cb + 1] = acc[mi][ni][1] + b1;
                }
                if (rB < NN) {
                    g_Q1[(size_t)rB * 128 + cb]     = acc[mi][ni][2] + b0;
                    g_Q1[(size_t)rB * 128 + cb + 1] = acc[mi][ni][3] + b1;
                }
            }
        }
    }

    // ---- vel = silu(h @ Wv1 + bv1) @ Wv2 + bv2 -> out[0..NN) ----
    {
#pragma unroll
        for (int a = 0; a < 2; a++)
#pragma unroll
            for (int b = 0; b < 4; b++)
#pragma unroll
                for (int c = 0; c < 4; c++) acc[a][b][c] = 0.0f;
        gemm_tiles(sAh, sAl, g_Wv1f, 8, 0, 8, wm, wn, lane, acc);
        float p[4] = {0.f, 0.f, 0.f, 0.f};
#pragma unroll
        for (int ni = 0; ni < 4; ni++) {
            int cb = wn * 32 + ni * 8 + tig * 2;
            float b0 = sBv1[cb], b1 = sBv1[cb + 1];
            float w0 = sWv2[cb], w1 = sWv2[cb + 1];
#pragma unroll
            for (int mi = 0; mi < 2; mi++) {
                p[mi * 2 + 0] += silu_f(acc[mi][ni][0] + b0) * w0
                               + silu_f(acc[mi][ni][1] + b1) * w1;
                p[mi * 2 + 1] += silu_f(acc[mi][ni][2] + b0) * w0
                               + silu_f(acc[mi][ni][3] + b1) * w1;
            }
        }
#pragma unroll
        for (int j = 0; j < 4; j++) {
            p[j] += __shfl_xor_sync(0xffffffffu, p[j], 1);
            p[j] += __shfl_xor_sync(0xffffffffu, p[j], 2);
        }
        __syncthreads();
        if (tig == 0) {
#pragma unroll
            for (int j = 0; j < 4; j++) {
                int rr = wm * 32 + (j >> 1) * 16 + (j & 1) * 8 + g;
                atomicAdd(&sVel[rr], p[j]);
            }
        }
        __syncthreads();
        if (t < 64) {
            int n = n0 + t;
            if (n < NN) out[n] = sVel[t] + bv2[0];
        }
    }
}

// ---------------- edge kernel: 64 sorted edges/CTA ------------------------
#define OFF_AH 0u
#define OFF_AL 17408u
#define OFF_M  34816u      // 64*132*4 = 33792
#define OFF_X  68608u
#define SMEM_EDGE_TOTAL 72960

__global__ __launch_bounds__(256, 2) void edge_kernel_mma(
    const float* __restrict__ coord_diff,
    const int* __restrict__ row, const int* __restrict__ col,
    const float* __restrict__ We1, const float* __restrict__ be1,
    const float* __restrict__ be2,
    const float* __restrict__ bc1, const float* __restrict__ Wc2)
{
    extern __shared__ __align__(16) char smem[];
    unsigned short* sAh = (unsigned short*)(smem + OFF_AH);
    unsigned short* sAl = (unsigned short*)(smem + OFF_AL);
    float* sM    = (float*)(smem + OFF_M);
    int*   sRow  = (int*)  (smem + OFF_X);
    int*   sCol  = (int*)  (smem + OFF_X + 256);
    float* sRad  = (float*)(smem + OFF_X + 512);
    float* sCD   = (float*)(smem + OFF_X + 768);
    float* sBe1  = (float*)(smem + OFF_X + 1536);
    float* sW256 = (float*)(smem + OFF_X + 2048);
    float* sBe2  = (float*)(smem + OFF_X + 2560);
    float* sBc1  = (float*)(smem + OFF_X + 3072);
    float* sWc2  = (float*)(smem + OFF_X + 3584);
    float* sCoef = (float*)(smem + OFF_X + 4096);

    const int t    = threadIdx.x;
    const int lane = t & 31;
    const int wid  = t >> 5;
    const int wm   = wid >> 2;
    const int wn   = wid & 3;
    const int g    = lane >> 2;
    const int tig  = lane & 3;
    const int e0   = blockIdx.x * 64;

    if (t < 64) {
        int eid = g_perm[e0 + t];         // sorted-by-row edge order
        sRow[t] = row[eid];
        sCol[t] = col[eid];
        float cx = coord_diff[eid * 3 + 0];
        float cy = coord_diff[eid * 3 + 1];
        float cz = coord_diff[eid * 3 + 2];
        sCD[t * 3 + 0] = cx; sCD[t * 3 + 1] = cy; sCD[t * 3 + 2] = cz;
        sRad[t] = cx * cx + cy * cy + cz * cz;
        sCoef[t] = 0.0f;
    }
    if (t < 128) {
        sBe1[t]  = be1[t];
        sW256[t] = We1[256 * 128 + t];
        sBe2[t]  = be2[t];
        sBc1[t]  = bc1[t];
        sWc2[t]  = Wc2[t];
    }
    __syncthreads();

    // ---- h1 = silu(P1[row] + P2[col] + rad*w256 + be1) -> A (K=128) ----
    for (int i = t; i < 64 * 32; i += 256) {
        int e = i >> 5;
        int k = (i & 31) * 4;
        float rad = sRad[e];
        float4 a = *(const float4*)(g_P1 + (size_t)sRow[e] * 128 + k);
        float4 b = *(const float4*)(g_P2 + (size_t)sCol[e] * 128 + k);
        float4 w = *(const float4*)(sW256 + k);
        float4 bb = *(const float4*)(sBe1 + k);
        float x0 = silu_f(a.x + b.x + rad * w.x + bb.x);
        float x1 = silu_f(a.y + b.y + rad * w.y + bb.y);
        float x2 = silu_f(a.z + b.z + rad * w.z + bb.z);
        float x3 = silu_f(a.w + b.w + rad * w.w + bb.w);
        uint32_t h0, l0, h1, l1;
        split_pack(x0, x1, h0, l0);
        split_pack(x2, x3, h1, l1);
        *(uint2*)(sAh + e * SAS + k) = make_uint2(h0, h1);
        *(uint2*)(sAl + e * SAS + k) = make_uint2(l0, l1);
    }
    __syncthreads();

    float acc[2][4][4];

    // ---- GEMM2: m = silu(h1 @ We2 + be2), K=128 ----
#pragma unroll
    for (int a = 0; a < 2; a++)
#pragma unroll
        for (int b = 0; b < 4; b++)
#pragma unroll
            for (int c = 0; c < 4; c++) acc[a][b][c] = 0.0f;
    gemm_tiles(sAh, sAl, g_We2f, 8, 0, 8, wm, wn, lane, acc);
    __syncthreads();

#pragma unroll
    for (int mi = 0; mi < 2; mi++) {
        int rA = wm * 32 + mi * 16 + g;
        int rB = rA + 8;
#pragma unroll
        for (int ni = 0; ni < 4; ni++) {
            int cb = wn * 32 + ni * 8 + tig * 2;
            float b0 = sBe2[cb], b1 = sBe2[cb + 1];
            float m0 = silu_f(acc[mi][ni][0] + b0);
            float m1 = silu_f(acc[mi][ni][1] + b1);
            float m2 = silu_f(acc[mi][ni][2] + b0);
            float m3 = silu_f(acc[mi][ni][3] + b1);
            sM[rA * SMS + cb] = m0;  sM[rA * SMS + cb + 1] = m1;
            sM[rB * SMS + cb] = m2;  sM[rB * SMS + cb + 1] = m3;
            uint32_t hi, lo;
            split_pack(m0, m1, hi, lo);
            *(uint32_t*)(sAh + rA * SAS + cb) = hi;
            *(uint32_t*)(sAl + rA * SAS + cb) = lo;
            split_pack(m2, m3, hi, lo);
            *(uint32_t*)(sAh + rB * SAS + cb) = hi;
            *(uint32_t*)(sAl + rB * SAS + cb) = lo;
        }
    }
    __syncthreads();

    // ---- segmented agg scatter: rows sorted -> one red.v4 per segment ----
    // warp w handles edges w, w+8, ..., lanes cover the 128 dims (d4).
#pragma unroll
    for (int it = 0; it < 8; it++) {
        int e  = wid + it * 8;            // warp-uniform
        int d4 = lane * 4;
        int r = sRow[e];
        bool leader = (e == 0) || (sRow[e - 1] != r);
        if (leader) {                     // warp-uniform branch
            float4 s = *(const float4*)(sM + e * SMS + d4);
            int j = e + 1;
            while (j < 64 && sRow[j] == r) {
                float4 v = *(const float4*)(sM + j * SMS + d4);
                s.x += v.x; s.y += v.y; s.z += v.z; s.w += v.w;
                j++;
            }
            red_add_v4(&g_agg[(size_t)r * 128 + d4], s);
        }
    }

    // ---- GEMM3: K=128 ----
#pragma unroll
    for (int a = 0; a < 2; a++)
#pragma unroll
        for (int b = 0; b < 4; b++)
#pragma unroll
            for (int c = 0; c < 4; c++) acc[a][b][c] = 0.0f;
    gemm_tiles(sAh, sAl, g_Wc1f, 8, 0, 8, wm, wn, lane, acc);

    // ---- epilogue3: coef = sum_n silu(D + bc1) * Wc2 ----
    {
        float p[4] = {0.f, 0.f, 0.f, 0.f};
#pragma unroll
        for (int ni = 0; ni < 4; ni++) {
            int cb = wn * 32 + ni * 8 + tig * 2;
            float b0 = sBc1[cb], b1 = sBc1[cb + 1];
            float w0 = sWc2[cb], w1 = sWc2[cb + 1];
#pragma unroll
            for (int mi = 0; mi < 2; mi++) {
                p[mi * 2 + 0] += silu_f(acc[mi][ni][0] + b0) * w0
                               + silu_f(acc[mi][ni][1] + b1) * w1;
                p[mi * 2 + 1] += silu_f(acc[mi][ni][2] + b0) * w0
                               + silu_f(acc[mi][ni][3] + b1) * w1;
            }
        }
#pragma unroll
        for (int j = 0; j < 4; j++) {
            p[j] += __shfl_xor_sync(0xffffffffu, p[j], 1);
            p[j] += __shfl_xor_sync(0xffffffffu, p[j], 2);
        }
        if (tig == 0) {
#pragma unroll
            for (int j = 0; j < 4; j++) {
                int rr = wm * 32 + (j >> 1) * 16 + (j & 1) * 8 + g;
                atomicAdd(&sCoef[rr], p[j]);
            }
        }
    }
    __syncthreads();

    // ---- force scatter: segmented over sorted rows (threads 0-63) ----
    if (t < 64) {
        int r = sRow[t];
        bool leader = (t == 0) || (sRow[t - 1] != r);
        if (leader) {
            float fx = 0.f, fy = 0.f, fz = 0.f;
            int j = t;
            do {
                float c = sCoef[j];
                float vx = sCD[j * 3 + 0] * c;
                float vy = sCD[j * 3 + 1] * c;
                float vz = sCD[j * 3 + 2] * c;
                fx += fminf(fmaxf(vx, -100.0f), 100.0f);
                fy += fminf(fmaxf(vy, -100.0f), 100.0f);
                fz += fminf(fmaxf(vz, -100.0f), 100.0f);
                j++;
            } while (j < 64 && sRow[j] == r);
            atomicAdd(&g_fsum[r * 3 + 0], fx);
            atomicAdd(&g_fsum[r * 3 + 1], fy);
            atomicAdd(&g_fsum[r * 3 + 2], fz);
        }
    }
}

// ---------------------------------------------------------------------------
// Node kernel: h_out = silu(Q1 + agg@Wn1_bot) @ Wn2 + bn2 ; force normalize
// out layout: [vel (N)] [force (N*3)] [h_out (N*128)]
// ---------------------------------------------------------------------------
__global__ __launch_bounds__(256, 3) void node_kernel(
    const float* __restrict__ Wn1, const float* __restrict__ Wn2,
    const float* __restrict__ bn2,
    float* __restrict__ out)
{
    extern __shared__ float sm[];
    float* sB = sm;              // 4096
    float* sA = sB + 4096;       // 2112
    float* sH = sA + 2112;       // 8448

    const int t    = threadIdx.x;
    const int lane = t & 31;
    const int warp = t >> 5;
    const int col0 = lane * 4;
    const int row0 = warp * 8;
    const int n0   = blockIdx.x * 64;

    float acc[8][4];

    // ---- GEMM1: acc = Q1 + agg @ Wn1_bot (K=128) ----
#pragma unroll
    for (int i = 0; i < 8; i++) {
        int n = n0 + row0 + i;
        if (n < NN) {
            float4 q = *(const float4*)(g_Q1 + (size_t)n * 128 + col0);
            acc[i][0] = q.x; acc[i][1] = q.y; acc[i][2] = q.z; acc[i][3] = q.w;
        } else {
            acc[i][0] = acc[i][1] = acc[i][2] = acc[i][3] = 0.0f;
        }
    }

    for (int kc = 0; kc < 4; kc++) {
        __syncthreads();
        const float4* Wsrc = (const float4*)(Wn1 + (128 + kc * 32) * 128);
        float4* Bdst = (float4*)sB;
        Bdst[t]       = Wsrc[t];
        Bdst[t + 256] = Wsrc[t + 256];
        Bdst[t + 512] = Wsrc[t + 512];
        Bdst[t + 768] = Wsrc[t + 768];
        {
            int e  = t >> 2;
            int kq = t & 3;
            int n  = n0 + e;
            float* dst = sA + e * 33 + kq * 8;
            if (n < NN) {
                int k = kc * 32 + kq * 8;
                float4 v  = *(const float4*)(g_agg + (size_t)n * 128 + k);
                float4 v2 = *(const float4*)(g_agg + (size_t)n * 128 + k + 4);
                dst[0] = v.x; dst[1] = v.y; dst[2] = v.z; dst[3] = v.w;
                dst[4] = v2.x; dst[5] = v2.y; dst[6] = v2.z; dst[7] = v2.w;
            } else {
#pragma unroll
                for (int q = 0; q < 8; q++) dst[q] = 0.0f;
            }
        }
        __syncthreads();
#pragma unroll
        for (int kk = 0; kk < 32; kk++) {
            float4 bv = *(const float4*)(sB + kk * 128 + col0);
#pragma unroll
            for (int i = 0; i < 8; i++) {
                float a = sA[(row0 + i) * 33 + kk];
                acc[i][0] += a * bv.x;
                acc[i][1] += a * bv.y;
                acc[i][2] += a * bv.z;
                acc[i][3] += a * bv.w;
            }
        }
    }
#pragma unroll
    for (int i = 0; i < 8; i++) {
        float4 v;
        v.x = silu_f(acc[i][0]); v.y = silu_f(acc[i][1]);
        v.z = silu_f(acc[i][2]); v.w = silu_f(acc[i][3]);
        *(float4*)(sH + (row0 + i) * 132 + col0) = v;
    }

    // ---- GEMM2: h_out = sH @ Wn2 + bn2 ----
#pragma unroll
    for (int i = 0; i < 8; i++)
#pragma unroll
        for (int j = 0; j < 4; j++) acc[i][j] = bn2[col0 + j];

    for (int kc = 0; kc < 4; kc++) {
        __syncthreads();
        const float4* Wsrc = (const float4*)(Wn2 + kc * 32 * 128);
        float4* Bdst = (float4*)sB;
        Bdst[t]       = Wsrc[t];
        Bdst[t + 256] = Wsrc[t + 256];
        Bdst[t + 512] = Wsrc[t + 512];
        Bdst[t + 768] = Wsrc[t + 768];
        __syncthreads();
#pragma unroll
        for (int kk = 0; kk < 32; kk++) {
            float4 bv = *(const float4*)(sB + kk * 128 + col0);
            int kg = kc * 32 + kk;
#pragma unroll
            for (int i = 0; i < 8; i++) {
                float a = sH[(row0 + i) * 132 + kg];
                acc[i][0] += a * bv.x;
                acc[i][1] += a * bv.y;
                acc[i][2] += a * bv.z;
                acc[i][3] += a * bv.w;
            }
        }
    }
    {
        float* outH = out + (size_t)4 * NN;
#pragma unroll
        for (int i = 0; i < 8; i++) {
            int n = n0 + row0 + i;
            if (n < NN) {
                float4 v;
                v.x = acc[i][0]; v.y = acc[i][1]; v.z = acc[i][2]; v.w = acc[i][3];
                *(float4*)(outH + (size_t)n * 128 + col0) = v;
            }
        }
    }

    // ---- force normalize (cnt from histogram) ----
    if (t < 64) {
        int n = n0 + t;
        if (n < NN) {
            float c = g_cnt[n];
            float inv = 1.0f / fmaxf(c, 1.0f);
            out[NN + (size_t)n * 3 + 0] = g_fsum[n * 3 + 0] * inv;
            out[NN + (size_t)n * 3 + 1] = g_fsum[n * 3 + 1] * inv;
            out[NN + (size_t)n * 3 + 2] = g_fsum[n * 3 + 2] * inv;
        }
    }
}

// ---------------------------------------------------------------------------
extern "C" void kernel_launch(void* const* d_in, const int* in_sizes, int n_in,
                              void* d_out, int out_size)
{
    const float* h          = (const float*)d_in[0];
    const float* coord_diff = (const float*)d_in[1];
    const int*   row        = (const int*)  d_in[2];
    const int*   col        = (const int*)  d_in[3];
    const float* We1 = (const float*)d_in[4];
    const float* be1 = (const float*)d_in[5];
    const float* We2 = (const float*)d_in[6];
    const float* be2 = (const float*)d_in[7];
    const float* Wn1 = (const float*)d_in[8];
    const float* bn1 = (const float*)d_in[9];
    const float* Wn2 = (const float*)d_in[10];
    const float* bn2 = (const float*)d_in[11];
    const float* Wc1 = (const float*)d_in[12];
    const float* bc1 = (const float*)d_in[13];
    const float* Wc2 = (const float*)d_in[14];
    const float* Wv1 = (const float*)d_in[15];
    const float* bv1 = (const float*)d_in[16];
    const float* Wv2 = (const float*)d_in[17];
    const float* bv2 = (const float*)d_in[18];
    float* out = (float*)d_out;

    void *aggp, *fsump, *histp;
    cudaGetSymbolAddress(&aggp, g_agg);
    cudaGetSymbolAddress(&fsump, g_fsum);
    cudaGetSymbolAddress(&histp, g_hist);
    cudaMemsetAsync(aggp,  0, (size_t)NN * 128 * sizeof(float));
    cudaMemsetAsync(fsump, 0, (size_t)NN * 3 * sizeof(float));
    cudaMemsetAsync(histp, 0, (size_t)NN * sizeof(int));

    prep_weights_f<<<384, 256>>>(We1, We2, Wc1, Wn1, Wv1);
    hist_kernel<<<(EE + 255) / 256, 256>>>(row);
    scan_kernel<<<1, 1024>>>();
    fill_kernel<<<(EE + 255) / 256, 256>>>(row);

    precompute_p<<<(NN + 63) / 64, 256, 36864>>>(h, bn1, bv1, Wv2, bv2, out);

    cudaFuncSetAttribute(edge_kernel_mma, cudaFuncAttributeMaxDynamicSharedMemorySize,
                         SMEM_EDGE_TOTAL);
    edge_kernel_mma<<<EE / 64, 256, SMEM_EDGE_TOTAL>>>(
        coord_diff, row, col, We1, be1, be2, bc1, Wc2);

    const size_t smN = (size_t)(4096 + 2112 + 8448) * sizeof(float);
    cudaFuncSetAttribute(node_kernel, cudaFuncAttributeMaxDynamicSharedMemorySize, (int)smN);
    node_kernel<<<(NN + 63) / 64, 256, smN>>>(Wn1, Wn2, bn2, out);
}

// round 12
// speedup vs baseline: 1.5063x; 1.4668x over previous
#include <cuda_runtime.h>
#include <cuda_bf16.h>
#include <cstdint>

#define NN 50000
#define EE 800000

// ---------------- scratch (__device__ globals; no allocs) ----------------
__device__ float g_agg[(size_t)NN * 128];
__device__ float g_fsum[NN * 3];
__device__ float g_cnt[NN];
__device__ float g_P1[(size_t)NN * 128];   // h @ We1[0:128,:]
__device__ float g_P2[(size_t)NN * 128];   // h @ We1[128:256,:]
__device__ float g_Q1[(size_t)NN * 128];   // h @ Wn1[0:128,:] + bn1

// Weight fragments for mma.sync m16n8k16 (bf16 hi/lo), per-lane order:
//   u32 index = ((hl*16 + nt)*KT + kt)*64 + lane*2 + r
__device__ __align__(16) uint2 g_We1f[16384];  // K=256
__device__ __align__(16) uint2 g_We2f[8192];   // K=128
__device__ __align__(16) uint2 g_Wc1f[8192];   // K=128
__device__ __align__(16) uint2 g_Wn1tf[8192];  // Wn1 top half, K=128
__device__ __align__(16) uint2 g_Wv1f[8192];   // Wv1, K=128

__device__ __forceinline__ float silu_f(float x) {
    return x / (1.0f + __expf(-x));
}

__device__ __forceinline__ void split_pack(float f0, float f1, uint32_t& hi, uint32_t& lo) {
    __nv_bfloat162 bh = __floats2bfloat162_rn(f0, f1);
    float2 bf = __bfloat1622float2(bh);
    __nv_bfloat162 bl = __floats2bfloat162_rn(f0 - bf.x, f1 - bf.y);
    hi = *(uint32_t*)&bh;
    lo = *(uint32_t*)&bl;
}

__device__ __forceinline__ void mma16816(float* c, const uint32_t* a, const uint32_t* b) {
    asm volatile(
        "mma.sync.aligned.m16n8k16.row.col.f32.bf16.bf16.f32 "
        "{%0,%1,%2,%3}, {%4,%5,%6,%7}, {%8,%9}, {%0,%1,%2,%3};"
        : "+f"(c[0]), "+f"(c[1]), "+f"(c[2]), "+f"(c[3])
        : "r"(a[0]), "r"(a[1]), "r"(a[2]), "r"(a[3]), "r"(b[0]), "r"(b[1]));
}

__device__ __forceinline__ void red_add_v2(float* gptr, float a, float b) {
    asm volatile("red.global.add.v2.f32 [%0], {%1, %2};"
                 :: "l"(gptr), "f"(a), "f"(b) : "memory");
}

#define SAS 136   // A stride (bf16) for K=128 tiles

// ---------------- prep: weights -> bf16 hi/lo fragment order --------------
__global__ void prep_weights_f(const float* __restrict__ We1,
                               const float* __restrict__ We2,
                               const float* __restrict__ Wc1,
                               const float* __restrict__ Wn1,
                               const float* __restrict__ Wv1) {
    int i = blockIdx.x * blockDim.x + threadIdx.x;
    const float* W; uint32_t* out; int KT, j;
    if (i < 32768)      { W = We1; out = (uint32_t*)g_We1f;  KT = 16; j = i; }
    else if (i < 49152) { W = We2; out = (uint32_t*)g_We2f;  KT = 8;  j = i - 32768; }
    else if (i < 65536) { W = Wc1; out = (uint32_t*)g_Wc1f;  KT = 8;  j = i - 49152; }
    else if (i < 81920) { W = Wn1; out = (uint32_t*)g_Wn1tf; KT = 8;  j = i - 65536; }
    else if (i < 98304) { W = Wv1; out = (uint32_t*)g_Wv1f;  KT = 8;  j = i - 81920; }
    else return;
    int per_hl = 16 * KT * 64;
    int hl = j / per_hl; int rem = j % per_hl;
    int nt = rem / (KT * 64); rem %= KT * 64;
    int kt = rem / 64; rem %= 64;
    int lane = rem >> 1, r = rem & 1;
    int g = lane >> 2, tig = lane & 3;
    int n = nt * 8 + g;
    int k = kt * 16 + tig * 2 + r * 8;
    float w0 = W[k * 128 + n], w1 = W[(k + 1) * 128 + n];
    __nv_bfloat162 p;
    if (hl == 0) {
        p.x = __float2bfloat16(w0);
        p.y = __float2bfloat16(w1);
    } else {
        __nv_bfloat16 h0 = __float2bfloat16(w0), h1 = __float2bfloat16(w1);
        p.x = __float2bfloat16(w0 - __bfloat162float(h0));
        p.y = __float2bfloat16(w1 - __bfloat162float(h1));
    }
    out[((hl * 16 + nt) * KT + kt) * 64 + lane * 2 + r] = *(uint32_t*)&p;
}

// ---------------- shared GEMM core: 2x4 mma tiles per warp ----------------
__device__ __forceinline__ void gemm_tiles(
    const unsigned short* __restrict__ sAh, const unsigned short* __restrict__ sAl,
    const uint2* __restrict__ Bf, int KTtot, int kt0, int ktn,
    int wm, int wn, int lane, float acc[2][4][4])
{
    const int g = lane >> 2, tig = lane & 3;
    const int m0 = wm * 32;
    for (int kti = 0; kti < ktn; kti++) {
        uint32_t ah[2][4], al[2][4];
        const int kb = kti * 16 + tig * 2;
#pragma unroll
        for (int mi = 0; mi < 2; mi++) {
            const unsigned short* p0 = sAh + (m0 + mi * 16 + g) * SAS + kb;
            const unsigned short* p1 = p0 + 8 * SAS;
            ah[mi][0] = *(const uint32_t*)p0;
            ah[mi][1] = *(const uint32_t*)p1;
            ah[mi][2] = *(const uint32_t*)(p0 + 8);
            ah[mi][3] = *(const uint32_t*)(p1 + 8);
            const unsigned short* q0 = sAl + (m0 + mi * 16 + g) * SAS + kb;
            const unsigned short* q1 = q0 + 8 * SAS;
            al[mi][0] = *(const uint32_t*)q0;
            al[mi][1] = *(const uint32_t*)q1;
            al[mi][2] = *(const uint32_t*)(q0 + 8);
            al[mi][3] = *(const uint32_t*)(q1 + 8);
        }
        const int kt = kt0 + kti;
#pragma unroll
        for (int ni = 0; ni < 4; ni++) {
            const int nt = wn * 4 + ni;
            uint2 bh = Bf[(nt * KTtot + kt) * 32 + lane];
            uint2 bl = Bf[((16 + nt) * KTtot + kt) * 32 + lane];
            uint32_t bhr[2] = {bh.x, bh.y};
            uint32_t blr[2] = {bl.x, bl.y};
            mma16816(acc[0][ni], ah[0], bhr);
            mma16816(acc[1][ni], ah[1], bhr);
            mma16816(acc[0][ni], al[0], bhr);
            mma16816(acc[1][ni], al[1], bhr);
            mma16816(acc[0][ni], ah[0], blr);
            mma16816(acc[1][ni], ah[1], blr);
        }
    }
}

// ---------------- precompute: P1, P2, Q1, vel — all h-only GEMMs ----------
__global__ __launch_bounds__(256, 2) void precompute_p(
    const float* __restrict__ h,
    const float* __restrict__ bn1,
    const float* __restrict__ bv1,
    const float* __restrict__ Wv2, const float* __restrict__ bv2,
    float* __restrict__ out)
{
    extern __shared__ __align__(16) char smem[];
    unsigned short* sAh = (unsigned short*)smem;
    unsigned short* sAl = (unsigned short*)(smem + 17408);
    float* sBn1 = (float*)(smem + 34816);
    float* sBv1 = (float*)(smem + 35328);
    float* sWv2 = (float*)(smem + 35840);
    float* sVel = (float*)(smem + 36352);

    const int t    = threadIdx.x;
    const int lane = t & 31;
    const int wid  = t >> 5;
    const int wm   = wid >> 2;
    const int wn   = wid & 3;
    const int g    = lane >> 2;
    const int tig  = lane & 3;
    const int n0   = blockIdx.x * 64;

    if (t < 128) {
        sBn1[t] = bn1[t];
        sBv1[t] = bv1[t];
        sWv2[t] = Wv2[t];
    }
    if (t < 64) sVel[t] = 0.0f;

    for (int i = t; i < 64 * 32; i += 256) {
        int e = i >> 5;
        int k = (i & 31) * 4;
        int n = n0 + e;
        float4 v = make_float4(0.f, 0.f, 0.f, 0.f);
        if (n < NN) v = *(const float4*)(h + (size_t)n * 128 + k);
        uint32_t h0, l0, h1, l1;
        split_pack(v.x, v.y, h0, l0);
        split_pack(v.z, v.w, h1, l1);
        *(uint2*)(sAh + e * SAS + k) = make_uint2(h0, h1);
        *(uint2*)(sAl + e * SAS + k) = make_uint2(l0, l1);
    }
    __syncthreads();

    float acc[2][4][4];

    // ---- P1, P2 (We1 halves) ----
#pragma unroll
    for (int p = 0; p < 2; p++) {
#pragma unroll
        for (int a = 0; a < 2; a++)
#pragma unroll
            for (int b = 0; b < 4; b++)
#pragma unroll
                for (int c = 0; c < 4; c++) acc[a][b][c] = 0.0f;
        gemm_tiles(sAh, sAl, g_We1f, 16, p * 8, 8, wm, wn, lane, acc);
        float* outp = p ? g_P2 : g_P1;
#pragma unroll
        for (int mi = 0; mi < 2; mi++) {
            int rA = n0 + wm * 32 + mi * 16 + g;
            int rB = rA + 8;
#pragma unroll
            for (int ni = 0; ni < 4; ni++) {
                int cb = wn * 32 + ni * 8 + tig * 2;
                if (rA < NN) {
                    outp[(size_t)rA * 128 + cb]     = acc[mi][ni][0];
                    outp[(size_t)rA * 128 + cb + 1] = acc[mi][ni][1];
                }
                if (rB < NN) {
                    outp[(size_t)rB * 128 + cb]     = acc[mi][ni][2];
                    outp[(size_t)rB * 128 + cb + 1] = acc[mi][ni][3];
                }
            }
        }
    }

    // ---- Q1 = h @ Wn1_top + bn1 ----
    {
#pragma unroll
        for (int a = 0; a < 2; a++)
#pragma unroll
            for (int b = 0; b < 4; b++)
#pragma unroll
                for (int c = 0; c < 4; c++) acc[a][b][c] = 0.0f;
        gemm_tiles(sAh, sAl, g_Wn1tf, 8, 0, 8, wm, wn, lane, acc);
#pragma unroll
        for (int mi = 0; mi < 2; mi++) {
            int rA = n0 + wm * 32 + mi * 16 + g;
            int rB = rA + 8;
#pragma unroll
            for (int ni = 0; ni < 4; ni++) {
                int cb = wn * 32 + ni * 8 + tig * 2;
                float b0 = sBn1[cb], b1 = sBn1[cb + 1];
                if (rA < NN) {
                    g_Q1[(size_t)rA * 128 + cb]     = acc[mi][ni][0] + b0;
                    g_Q1[(size_t)rA * 128 + cb + 1] = acc[mi][ni][1] + b1;
                }
                if (rB < NN) {
                    g_Q1[(size_t)rB * 128 + cb]     = acc[mi][ni][2] + b0;
                    g_Q1[(size_t)rB * 128 + cb + 1] = acc[mi][ni][3] + b1;
                }
            }
        }
    }

    // ---- vel = silu(h @ Wv1 + bv1) @ Wv2 + bv2 -> out[0..NN) ----
    {
#pragma unroll
        for (int a = 0; a < 2; a++)
#pragma unroll
            for (int b = 0; b < 4; b++)
#pragma unroll
                for (int c = 0; c < 4; c++) acc[a][b][c] = 0.0f;
        gemm_tiles(sAh, sAl, g_Wv1f, 8, 0, 8, wm, wn, lane, acc);
        float p[4] = {0.f, 0.f, 0.f, 0.f};
#pragma unroll
        for (int ni = 0; ni < 4; ni++) {
            int cb = wn * 32 + ni * 8 + tig * 2;
            float b0 = sBv1[cb], b1 = sBv1[cb + 1];
            float w0 = sWv2[cb], w1 = sWv2[cb + 1];
#pragma unroll
            for (int mi = 0; mi < 2; mi++) {
                p[mi * 2 + 0] += silu_f(acc[mi][ni][0] + b0) * w0
                               + silu_f(acc[mi][ni][1] + b1) * w1;
                p[mi * 2 + 1] += silu_f(acc[mi][ni][2] + b0) * w0
                               + silu_f(acc[mi][ni][3] + b1) * w1;
            }
        }
#pragma unroll
        for (int j = 0; j < 4; j++) {
            p[j] += __shfl_xor_sync(0xffffffffu, p[j], 1);
            p[j] += __shfl_xor_sync(0xffffffffu, p[j], 2);
        }
        __syncthreads();
        if (tig == 0) {
#pragma unroll
            for (int j = 0; j < 4; j++) {
                int rr = wm * 32 + (j >> 1) * 16 + (j & 1) * 8 + g;
                atomicAdd(&sVel[rr], p[j]);
            }
        }
        __syncthreads();
        if (t < 64) {
            int n = n0 + t;
            if (n < NN) out[n] = sVel[t] + bv2[0];
        }
    }
}

// ---------------- edge kernel: 64 edges/CTA, 3 CTAs/SM --------------------
#define OFF_AH 0u          // 17408
#define OFF_AL 17408u      // 17408
#define OFF_X  34816u      // misc 4352
#define SMEM_EDGE_TOTAL 39168

__global__ __launch_bounds__(256, 3) void edge_kernel_mma(
    const float* __restrict__ coord_diff,
    const int* __restrict__ row, const int* __restrict__ col,
    const float* __restrict__ We1, const float* __restrict__ be1,
    const float* __restrict__ be2,
    const float* __restrict__ bc1, const float* __restrict__ Wc2)
{
    extern __shared__ __align__(16) char smem[];
    unsigned short* sAh = (unsigned short*)(smem + OFF_AH);
    unsigned short* sAl = (unsigned short*)(smem + OFF_AL);
    int*   sRow  = (int*)  (smem + OFF_X);
    int*   sCol  = (int*)  (smem + OFF_X + 256);
    float* sRad  = (float*)(smem + OFF_X + 512);
    float* sCD   = (float*)(smem + OFF_X + 768);
    float* sBe1  = (float*)(smem + OFF_X + 1536);
    float* sW256 = (float*)(smem + OFF_X + 2048);
    float* sBe2  = (float*)(smem + OFF_X + 2560);
    float* sBc1  = (float*)(smem + OFF_X + 3072);
    float* sWc2  = (float*)(smem + OFF_X + 3584);
    float* sCoef = (float*)(smem + OFF_X + 4096);

    const int t    = threadIdx.x;
    const int lane = t & 31;
    const int wid  = t >> 5;
    const int wm   = wid >> 2;
    const int wn   = wid & 3;
    const int g    = lane >> 2;
    const int tig  = lane & 3;
    const int e0   = blockIdx.x * 64;

    if (t < 64) {
        int e = e0 + t;
        sRow[t] = row[e];
        sCol[t] = col[e];
        float cx = coord_diff[e * 3 + 0];
        float cy = coord_diff[e * 3 + 1];
        float cz = coord_diff[e * 3 + 2];
        sCD[t * 3 + 0] = cx; sCD[t * 3 + 1] = cy; sCD[t * 3 + 2] = cz;
        sRad[t] = cx * cx + cy * cy + cz * cz;
        sCoef[t] = 0.0f;
    }
    if (t < 128) {
        sBe1[t]  = be1[t];
        sW256[t] = We1[256 * 128 + t];
        sBe2[t]  = be2[t];
        sBc1[t]  = bc1[t];
        sWc2[t]  = Wc2[t];
    }
    __syncthreads();

    // ---- h1 = silu(P1[row] + P2[col] + rad*w256 + be1) -> A (K=128) ----
    for (int i = t; i < 64 * 32; i += 256) {
        int e = i >> 5;
        int k = (i & 31) * 4;
        float rad = sRad[e];
        float4 a = *(const float4*)(g_P1 + (size_t)sRow[e] * 128 + k);
        float4 b = *(const float4*)(g_P2 + (size_t)sCol[e] * 128 + k);
        float4 w = *(const float4*)(sW256 + k);
        float4 bb = *(const float4*)(sBe1 + k);
        float x0 = silu_f(a.x + b.x + rad * w.x + bb.x);
        float x1 = silu_f(a.y + b.y + rad * w.y + bb.y);
        float x2 = silu_f(a.z + b.z + rad * w.z + bb.z);
        float x3 = silu_f(a.w + b.w + rad * w.w + bb.w);
        uint32_t h0, l0, h1, l1;
        split_pack(x0, x1, h0, l0);
        split_pack(x2, x3, h1, l1);
        *(uint2*)(sAh + e * SAS + k) = make_uint2(h0, h1);
        *(uint2*)(sAl + e * SAS + k) = make_uint2(l0, l1);
    }
    __syncthreads();

    float acc[2][4][4];

    // ---- GEMM2: m = silu(h1 @ We2 + be2), K=128 ----
#pragma unroll
    for (int a = 0; a < 2; a++)
#pragma unroll
        for (int b = 0; b < 4; b++)
#pragma unroll
            for (int c = 0; c < 4; c++) acc[a][b][c] = 0.0f;
    gemm_tiles(sAh, sAl, g_We2f, 8, 0, 8, wm, wn, lane, acc);
    __syncthreads();

    // ---- epilogue2: m = silu(D+be2); RED to g_agg from regs; bf16 -> A ----
#pragma unroll
    for (int mi = 0; mi < 2; mi++) {
        int rA = wm * 32 + mi * 16 + g;
        int rB = rA + 8;
        int rowA = sRow[rA], rowB = sRow[rB];
#pragma unroll
        for (int ni = 0; ni < 4; ni++) {
            int cb = wn * 32 + ni * 8 + tig * 2;
            float b0 = sBe2[cb], b1 = sBe2[cb + 1];
            float m0 = silu_f(acc[mi][ni][0] + b0);
            float m1 = silu_f(acc[mi][ni][1] + b1);
            float m2 = silu_f(acc[mi][ni][2] + b0);
            float m3 = silu_f(acc[mi][ni][3] + b1);
            red_add_v2(&g_agg[(size_t)rowA * 128 + cb], m0, m1);
            red_add_v2(&g_agg[(size_t)rowB * 128 + cb], m2, m3);
            uint32_t hi, lo;
            split_pack(m0, m1, hi, lo);
            *(uint32_t*)(sAh + rA * SAS + cb) = hi;
            *(uint32_t*)(sAl + rA * SAS + cb) = lo;
            split_pack(m2, m3, hi, lo);
            *(uint32_t*)(sAh + rB * SAS + cb) = hi;
            *(uint32_t*)(sAl + rB * SAS + cb) = lo;
        }
    }
    __syncthreads();

    // ---- GEMM3: K=128 ----
#pragma unroll
    for (int a = 0; a < 2; a++)
#pragma unroll
        for (int b = 0; b < 4; b++)
#pragma unroll
            for (int c = 0; c < 4; c++) acc[a][b][c] = 0.0f;
    gemm_tiles(sAh, sAl, g_Wc1f, 8, 0, 8, wm, wn, lane, acc);

    // ---- epilogue3: coef = sum_n silu(D + bc1) * Wc2 ----
    {
        float p[4] = {0.f, 0.f, 0.f, 0.f};
#pragma unroll
        for (int ni = 0; ni < 4; ni++) {
            int cb = wn * 32 + ni * 8 + tig * 2;
            float b0 = sBc1[cb], b1 = sBc1[cb + 1];
            float w0 = sWc2[cb], w1 = sWc2[cb + 1];
#pragma unroll
            for (int mi = 0; mi < 2; mi++) {
                p[mi * 2 + 0] += silu_f(acc[mi][ni][0] + b0) * w0
                               + silu_f(acc[mi][ni][1] + b1) * w1;
                p[mi * 2 + 1] += silu_f(acc[mi][ni][2] + b0) * w0
                               + silu_f(acc[mi][ni][3] + b1) * w1;
            }
        }
#pragma unroll
        for (int j = 0; j < 4; j++) {
            p[j] += __shfl_xor_sync(0xffffffffu, p[j], 1);
            p[j] += __shfl_xor_sync(0xffffffffu, p[j], 2);
        }
        if (tig == 0) {
#pragma unroll
            for (int j = 0; j < 4; j++) {
                int rr = wm * 32 + (j >> 1) * 16 + (j & 1) * 8 + g;
                atomicAdd(&sCoef[rr], p[j]);
            }
        }
    }
    __syncthreads();

    // ---- force scatter ----
    if (t < 64) {
        int r = sRow[t];
        float c = sCoef[t];
#pragma unroll
        for (int q = 0; q < 3; q++) {
            float v = sCD[t * 3 + q] * c;
            v = fminf(fmaxf(v, -100.0f), 100.0f);
            atomicAdd(&g_fsum[r * 3 + q], v);
        }
        atomicAdd(&g_cnt[r], 1.0f);
    }
}

// ---------------------------------------------------------------------------
// Node kernel: h_out = silu(Q1 + agg@Wn1_bot) @ Wn2 + bn2 ; force normalize
// out layout: [vel (N)] [force (N*3)] [h_out (N*128)]
// ---------------------------------------------------------------------------
__global__ __launch_bounds__(256, 3) void node_kernel(
    const float* __restrict__ Wn1, const float* __restrict__ Wn2,
    const float* __restrict__ bn2,
    float* __restrict__ out)
{
    extern __shared__ float sm[];
    float* sB = sm;              // 4096
    float* sA = sB + 4096;       // 2112
    float* sH = sA + 2112;       // 8448

    const int t    = threadIdx.x;
    const int lane = t & 31;
    const int warp = t >> 5;
    const int col0 = lane * 4;
    const int row0 = warp * 8;
    const int n0   = blockIdx.x * 64;

    float acc[8][4];

    // ---- GEMM1: acc = Q1 + agg @ Wn1_bot (K=128) ----
#pragma unroll
    for (int i = 0; i < 8; i++) {
        int n = n0 + row0 + i;
        if (n < NN) {
            float4 q = *(const float4*)(g_Q1 + (size_t)n * 128 + col0);
            acc[i][0] = q.x; acc[i][1] = q.y; acc[i][2] = q.z; acc[i][3] = q.w;
        } else {
            acc[i][0] = acc[i][1] = acc[i][2] = acc[i][3] = 0.0f;
        }
    }

    for (int kc = 0; kc < 4; kc++) {
        __syncthreads();
        const float4* Wsrc = (const float4*)(Wn1 + (128 + kc * 32) * 128);
        float4* Bdst = (float4*)sB;
        Bdst[t]       = Wsrc[t];
        Bdst[t + 256] = Wsrc[t + 256];
        Bdst[t + 512] = Wsrc[t + 512];
        Bdst[t + 768] = Wsrc[t + 768];
        {
            int e  = t >> 2;
            int kq = t & 3;
            int n  = n0 + e;
            float* dst = sA + e * 33 + kq * 8;
            if (n < NN) {
                int k = kc * 32 + kq * 8;
                float4 v  = *(const float4*)(g_agg + (size_t)n * 128 + k);
                float4 v2 = *(const float4*)(g_agg + (size_t)n * 128 + k + 4);
                dst[0] = v.x; dst[1] = v.y; dst[2] = v.z; dst[3] = v.w;
                dst[4] = v2.x; dst[5] = v2.y; dst[6] = v2.z; dst[7] = v2.w;
            } else {
#pragma unroll
                for (int q = 0; q < 8; q++) dst[q] = 0.0f;
            }
        }
        __syncthreads();
#pragma unroll
        for (int kk = 0; kk < 32; kk++) {
            float4 bv = *(const float4*)(sB + kk * 128 + col0);
#pragma unroll
            for (int i = 0; i < 8; i++) {
                float a = sA[(row0 + i) * 33 + kk];
                acc[i][0] += a * bv.x;
                acc[i][1] += a * bv.y;
                acc[i][2] += a * bv.z;
                acc[i][3] += a * bv.w;
            }
        }
    }
#pragma unroll
    for (int i = 0; i < 8; i++) {
        float4 v;
        v.x = silu_f(acc[i][0]); v.y = silu_f(acc[i][1]);
        v.z = silu_f(acc[i][2]); v.w = silu_f(acc[i][3]);
        *(float4*)(sH + (row0 + i) * 132 + col0) = v;
    }

    // ---- GEMM2: h_out = sH @ Wn2 + bn2 ----
#pragma unroll
    for (int i = 0; i < 8; i++)
#pragma unroll
        for (int j = 0; j < 4; j++) acc[i][j] = bn2[col0 + j];

    for (int kc = 0; kc < 4; kc++) {
        __syncthreads();
        const float4* Wsrc = (const float4*)(Wn2 + kc * 32 * 128);
        float4* Bdst = (float4*)sB;
        Bdst[t]       = Wsrc[t];
        Bdst[t + 256] = Wsrc[t + 256];
        Bdst[t + 512] = Wsrc[t + 512];
        Bdst[t + 768] = Wsrc[t + 768];
        __syncthreads();
#pragma unroll
        for (int kk = 0; kk < 32; kk++) {
            float4 bv = *(const float4*)(sB + kk * 128 + col0);
            int kg = kc * 32 + kk;
#pragma unroll
            for (int i = 0; i < 8; i++) {
                float a = sH[(row0 + i) * 132 + kg];
                acc[i][0] += a * bv.x;
                acc[i][1] += a * bv.y;
                acc[i][2] += a * bv.z;
                acc[i][3] += a * bv.w;
            }
        }
    }
    {
        float* outH = out + (size_t)4 * NN;
#pragma unroll
        for (int i = 0; i < 8; i++) {
            int n = n0 + row0 + i;
            if (n < NN) {
                float4 v;
                v.x = acc[i][0]; v.y = acc[i][1]; v.z = acc[i][2]; v.w = acc[i][3];
                *(float4*)(outH + (size_t)n * 128 + col0) = v;
            }
        }
    }

    // ---- force normalize ----
    if (t < 64) {
        int n = n0 + t;
        if (n < NN) {
            float c = g_cnt[n];
            float inv = 1.0f / fmaxf(c, 1.0f);
            out[NN + (size_t)n * 3 + 0] = g_fsum[n * 3 + 0] * inv;
            out[NN + (size_t)n * 3 + 1] = g_fsum[n * 3 + 1] * inv;
            out[NN + (size_t)n * 3 + 2] = g_fsum[n * 3 + 2] * inv;
        }
    }
}

// ---------------------------------------------------------------------------
extern "C" void kernel_launch(void* const* d_in, const int* in_sizes, int n_in,
                              void* d_out, int out_size)
{
    const float* h          = (const float*)d_in[0];
    const float* coord_diff = (const float*)d_in[1];
    const int*   row        = (const int*)  d_in[2];
    const int*   col        = (const int*)  d_in[3];
    const float* We1 = (const float*)d_in[4];
    const float* be1 = (const float*)d_in[5];
    const float* We2 = (const float*)d_in[6];
    const float* be2 = (const float*)d_in[7];
    const float* Wn1 = (const float*)d_in[8];
    const float* bn1 = (const float*)d_in[9];
    const float* Wn2 = (const float*)d_in[10];
    const float* bn2 = (const float*)d_in[11];
    const float* Wc1 = (const float*)d_in[12];
    const float* bc1 = (const float*)d_in[13];
    const float* Wc2 = (const float*)d_in[14];
    const float* Wv1 = (const float*)d_in[15];
    const float* bv1 = (const float*)d_in[16];
    const float* Wv2 = (const float*)d_in[17];
    const float* bv2 = (const float*)d_in[18];
    float* out = (float*)d_out;

    void *aggp, *fsump, *cntp;
    cudaGetSymbolAddress(&aggp, g_agg);
    cudaGetSymbolAddress(&fsump, g_fsum);
    cudaGetSymbolAddress(&cntp, g_cnt);
    cudaMemsetAsync(aggp,  0, (size_t)NN * 128 * sizeof(float));
    cudaMemsetAsync(fsump, 0, (size_t)NN * 3 * sizeof(float));
    cudaMemsetAsync(cntp,  0, (size_t)NN * sizeof(float));

    prep_weights_f<<<384, 256>>>(We1, We2, Wc1, Wn1, Wv1);

    precompute_p<<<(NN + 63) / 64, 256, 36864>>>(h, bn1, bv1, Wv2, bv2, out);

    cudaFuncSetAttribute(edge_kernel_mma, cudaFuncAttributeMaxDynamicSharedMemorySize,
                         SMEM_EDGE_TOTAL);
    edge_kernel_mma<<<EE / 64, 256, SMEM_EDGE_TOTAL>>>(
        coord_diff, row, col, We1, be1, be2, bc1, Wc2);

    const size_t smN = (size_t)(4096 + 2112 + 8448) * sizeof(float);
    cudaFuncSetAttribute(node_kernel, cudaFuncAttributeMaxDynamicSharedMemorySize, (int)smN);
    node_kernel<<<(NN + 63) / 64, 256, smN>>>(Wn1, Wn2, bn2, out);
}

// round 13
// speedup vs baseline: 1.6629x; 1.1040x over previous
#include <cuda_runtime.h>
#include <cuda_bf16.h>
#include <cstdint>

#define NN 50000
#define EE 800000

// ---------------- scratch (__device__ globals; no allocs) ----------------
__device__ float g_agg[(size_t)NN * 128];
__device__ float g_fsum[NN * 3];
__device__ float g_cnt[NN];
__device__ float g_P1[(size_t)NN * 128];   // h @ We1[0:128,:]
__device__ float g_P2[(size_t)NN * 128];   // h @ We1[128:256,:]
__device__ float g_Q1[(size_t)NN * 128];   // h @ Wn1[0:128,:] + bn1

// Weight fragments for mma.sync m16n8k16 (bf16 hi/lo), per-lane order:
//   u32 index = ((hl*16 + nt)*KT + kt)*64 + lane*2 + r
__device__ __align__(16) uint2 g_We1f[16384];  // K=256
__device__ __align__(16) uint2 g_We2f[8192];   // K=128
__device__ __align__(16) uint2 g_Wc1f[8192];   // K=128
__device__ __align__(16) uint2 g_Wn1tf[8192];  // Wn1 top half, K=128
__device__ __align__(16) uint2 g_Wv1f[8192];   // Wv1, K=128
__device__ __align__(16) uint2 g_Wn1bf[8192];  // Wn1 bottom half, K=128
__device__ __align__(16) uint2 g_Wn2f[8192];   // Wn2, K=128

__device__ __forceinline__ float silu_f(float x) {
    return x / (1.0f + __expf(-x));
}

__device__ __forceinline__ void split_pack(float f0, float f1, uint32_t& hi, uint32_t& lo) {
    __nv_bfloat162 bh = __floats2bfloat162_rn(f0, f1);
    float2 bf = __bfloat1622float2(bh);
    __nv_bfloat162 bl = __floats2bfloat162_rn(f0 - bf.x, f1 - bf.y);
    hi = *(uint32_t*)&bh;
    lo = *(uint32_t*)&bl;
}

__device__ __forceinline__ void mma16816(float* c, const uint32_t* a, const uint32_t* b) {
    asm volatile(
        "mma.sync.aligned.m16n8k16.row.col.f32.bf16.bf16.f32 "
        "{%0,%1,%2,%3}, {%4,%5,%6,%7}, {%8,%9}, {%0,%1,%2,%3};"
        : "+f"(c[0]), "+f"(c[1]), "+f"(c[2]), "+f"(c[3])
        : "r"(a[0]), "r"(a[1]), "r"(a[2]), "r"(a[3]), "r"(b[0]), "r"(b[1]));
}

__device__ __forceinline__ void red_add_v2(float* gptr, float a, float b) {
    asm volatile("red.global.add.v2.f32 [%0], {%1, %2};"
                 :: "l"(gptr), "f"(a), "f"(b) : "memory");
}

__device__ __forceinline__ void ldsm4(uint32_t* r, uint32_t saddr) {
    asm volatile("ldmatrix.sync.aligned.m8n8.x4.shared.b16 {%0,%1,%2,%3}, [%4];"
                 : "=r"(r[0]), "=r"(r[1]), "=r"(r[2]), "=r"(r[3]) : "r"(saddr));
}

#define SAS 136   // A stride (bf16) for K=128 tiles; 272B/row, 16B-aligned

// ---------------- prep: weights -> bf16 hi/lo fragment order --------------
__global__ void prep_weights_f(const float* __restrict__ We1,
                               const float* __restrict__ We2,
                               const float* __restrict__ Wc1,
                               const float* __restrict__ Wn1,
                               const float* __restrict__ Wv1,
                               const float* __restrict__ Wn2) {
    int i = blockIdx.x * blockDim.x + threadIdx.x;
    const float* W; uint32_t* out; int KT, j;
    if (i < 32768)       { W = We1;             out = (uint32_t*)g_We1f;  KT = 16; j = i; }
    else if (i < 49152)  { W = We2;             out = (uint32_t*)g_We2f;  KT = 8;  j = i - 32768; }
    else if (i < 65536)  { W = Wc1;             out = (uint32_t*)g_Wc1f;  KT = 8;  j = i - 49152; }
    else if (i < 81920)  { W = Wn1;             out = (uint32_t*)g_Wn1tf; KT = 8;  j = i - 65536; }
    else if (i < 98304)  { W = Wv1;             out = (uint32_t*)g_Wv1f;  KT = 8;  j = i - 81920; }
    else if (i < 114688) { W = Wn1 + 128 * 128; out = (uint32_t*)g_Wn1bf; KT = 8;  j = i - 98304; }
    else if (i < 131072) { W = Wn2;             out = (uint32_t*)g_Wn2f;  KT = 8;  j = i - 114688; }
    else return;
    int per_hl = 16 * KT * 64;
    int hl = j / per_hl; int rem = j % per_hl;
    int nt = rem / (KT * 64); rem %= KT * 64;
    int kt = rem / 64; rem %= 64;
    int lane = rem >> 1, r = rem & 1;
    int g = lane >> 2, tig = lane & 3;
    int n = nt * 8 + g;
    int k = kt * 16 + tig * 2 + r * 8;
    float w0 = W[k * 128 + n], w1 = W[(k + 1) * 128 + n];
    __nv_bfloat162 p;
    if (hl == 0) {
        p.x = __float2bfloat16(w0);
        p.y = __float2bfloat16(w1);
    } else {
        __nv_bfloat16 h0 = __float2bfloat16(w0), h1 = __float2bfloat16(w1);
        p.x = __float2bfloat16(w0 - __bfloat162float(h0));
        p.y = __float2bfloat16(w1 - __bfloat162float(h1));
    }
    out[((hl * 16 + nt) * KT + kt) * 64 + lane * 2 + r] = *(uint32_t*)&p;
}

// ---------------- shared GEMM core: 2x4 mma tiles per warp (LDSM A) -------
__device__ __forceinline__ void gemm_tiles(
    const unsigned short* __restrict__ sAh, const unsigned short* __restrict__ sAl,
    const uint2* __restrict__ Bf, int KTtot, int kt0, int ktn,
    int wm, int wn, int lane, float acc[2][4][4])
{
    const int m0 = wm * 32;
    // ldmatrix address per lane: lanes 0-15 -> rows (lane&15), lanes 16-31 -> col +8
    const int rsel = lane & 15;
    const int csel = ((lane >> 4) & 1) * 8;
    const uint32_t bH0 = (uint32_t)__cvta_generic_to_shared(sAh + (m0 + rsel) * SAS + csel);
    const uint32_t bH1 = (uint32_t)__cvta_generic_to_shared(sAh + (m0 + 16 + rsel) * SAS + csel);
    const uint32_t bL0 = (uint32_t)__cvta_generic_to_shared(sAl + (m0 + rsel) * SAS + csel);
    const uint32_t bL1 = (uint32_t)__cvta_generic_to_shared(sAl + (m0 + 16 + rsel) * SAS + csel);

    for (int kti = 0; kti < ktn; kti++) {
        uint32_t ah[2][4], al[2][4];
        const uint32_t koff = (uint32_t)kti * 32;   // 16 bf16 = 32 bytes
        ldsm4(ah[0], bH0 + koff);
        ldsm4(ah[1], bH1 + koff);
        ldsm4(al[0], bL0 + koff);
        ldsm4(al[1], bL1 + koff);
        const int kt = kt0 + kti;
#pragma unroll
        for (int ni = 0; ni < 4; ni++) {
            const int nt = wn * 4 + ni;
            uint2 bh = Bf[(nt * KTtot + kt) * 32 + lane];
            uint2 bl = Bf[((16 + nt) * KTtot + kt) * 32 + lane];
            uint32_t bhr[2] = {bh.x, bh.y};
            uint32_t blr[2] = {bl.x, bl.y};
            mma16816(acc[0][ni], ah[0], bhr);
            mma16816(acc[1][ni], ah[1], bhr);
            mma16816(acc[0][ni], al[0], bhr);
            mma16816(acc[1][ni], al[1], bhr);
            mma16816(acc[0][ni], ah[0], blr);
            mma16816(acc[1][ni], ah[1], blr);
        }
    }
}

// ---------------- precompute: P1, P2, Q1, vel — all h-only GEMMs ----------
__global__ __launch_bounds__(256, 2) void precompute_p(
    const float* __restrict__ h,
    const float* __restrict__ bn1,
    const float* __restrict__ bv1,
    const float* __restrict__ Wv2, const float* __restrict__ bv2,
    float* __restrict__ out)
{
    extern __shared__ __align__(16) char smem[];
    unsigned short* sAh = (unsigned short*)smem;
    unsigned short* sAl = (unsigned short*)(smem + 17408);
    float* sBn1 = (float*)(smem + 34816);
    float* sBv1 = (float*)(smem + 35328);
    float* sWv2 = (float*)(smem + 35840);
    float* sVel = (float*)(smem + 36352);

    const int t    = threadIdx.x;
    const int lane = t & 31;
    const int wid  = t >> 5;
    const int wm   = wid >> 2;
    const int wn   = wid & 3;
    const int g    = lane >> 2;
    const int tig  = lane & 3;
    const int n0   = blockIdx.x * 64;

    if (t < 128) {
        sBn1[t] = bn1[t];
        sBv1[t] = bv1[t];
        sWv2[t] = Wv2[t];
    }
    if (t < 64) sVel[t] = 0.0f;

    for (int i = t; i < 64 * 32; i += 256) {
        int e = i >> 5;
        int k = (i & 31) * 4;
        int n = n0 + e;
        float4 v = make_float4(0.f, 0.f, 0.f, 0.f);
        if (n < NN) v = *(const float4*)(h + (size_t)n * 128 + k);
        uint32_t h0, l0, h1, l1;
        split_pack(v.x, v.y, h0, l0);
        split_pack(v.z, v.w, h1, l1);
        *(uint2*)(sAh + e * SAS + k) = make_uint2(h0, h1);
        *(uint2*)(sAl + e * SAS + k) = make_uint2(l0, l1);
    }
    __syncthreads();

    float acc[2][4][4];

    // ---- P1, P2 (We1 halves) ----
#pragma unroll
    for (int p = 0; p < 2; p++) {
#pragma unroll
        for (int a = 0; a < 2; a++)
#pragma unroll
            for (int b = 0; b < 4; b++)
#pragma unroll
                for (int c = 0; c < 4; c++) acc[a][b][c] = 0.0f;
        gemm_tiles(sAh, sAl, g_We1f, 16, p * 8, 8, wm, wn, lane, acc);
        float* outp = p ? g_P2 : g_P1;
#pragma unroll
        for (int mi = 0; mi < 2; mi++) {
            int rA = n0 + wm * 32 + mi * 16 + g;
            int rB = rA + 8;
#pragma unroll
            for (int ni = 0; ni < 4; ni++) {
                int cb = wn * 32 + ni * 8 + tig * 2;
                if (rA < NN) {
                    outp[(size_t)rA * 128 + cb]     = acc[mi][ni][0];
                    outp[(size_t)rA * 128 + cb + 1] = acc[mi][ni][1];
                }
                if (rB < NN) {
                    outp[(size_t)rB * 128 + cb]     = acc[mi][ni][2];
                    outp[(size_t)rB * 128 + cb + 1] = acc[mi][ni][3];
                }
            }
        }
    }

    // ---- Q1 = h @ Wn1_top + bn1 ----
    {
#pragma unroll
        for (int a = 0; a < 2; a++)
#pragma unroll
            for (int b = 0; b < 4; b++)
#pragma unroll
                for (int c = 0; c < 4; c++) acc[a][b][c] = 0.0f;
        gemm_tiles(sAh, sAl, g_Wn1tf, 8, 0, 8, wm, wn, lane, acc);
#pragma unroll
        for (int mi = 0; mi < 2; mi++) {
            int rA = n0 + wm * 32 + mi * 16 + g;
            int rB = rA + 8;
#pragma unroll
            for (int ni = 0; ni < 4; ni++) {
                int cb = wn * 32 + ni * 8 + tig * 2;
                float b0 = sBn1[cb], b1 = sBn1[cb + 1];
                if (rA < NN) {
                    g_Q1[(size_t)rA * 128 + cb]     = acc[mi][ni][0] + b0;
                    g_Q1[(size_t)rA * 128 + cb + 1] = acc[mi][ni][1] + b1;
                }
                if (rB < NN) {
                    g_Q1[(size_t)rB * 128 + cb]     = acc[mi][ni][2] + b0;
                    g_Q1[(size_t)rB * 128 + cb + 1] = acc[mi][ni][3] + b1;
                }
            }
        }
    }

    // ---- vel = silu(h @ Wv1 + bv1) @ Wv2 + bv2 -> out[0..NN) ----
    {
#pragma unroll
        for (int a = 0; a < 2; a++)
#pragma unroll
            for (int b = 0; b < 4; b++)
#pragma unroll
                for (int c = 0; c < 4; c++) acc[a][b][c] = 0.0f;
        gemm_tiles(sAh, sAl, g_Wv1f, 8, 0, 8, wm, wn, lane, acc);
        float p[4] = {0.f, 0.f, 0.f, 0.f};
#pragma unroll
        for (int ni = 0; ni < 4; ni++) {
            int cb = wn * 32 + ni * 8 + tig * 2;
            float b0 = sBv1[cb], b1 = sBv1[cb + 1];
            float w0 = sWv2[cb], w1 = sWv2[cb + 1];
#pragma unroll
            for (int mi = 0; mi < 2; mi++) {
                p[mi * 2 + 0] += silu_f(acc[mi][ni][0] + b0) * w0
                               + silu_f(acc[mi][ni][1] + b1) * w1;
                p[mi * 2 + 1] += silu_f(acc[mi][ni][2] + b0) * w0
                               + silu_f(acc[mi][ni][3] + b1) * w1;
            }
        }
#pragma unroll
        for (int j = 0; j < 4; j++) {
            p[j] += __shfl_xor_sync(0xffffffffu, p[j], 1);
            p[j] += __shfl_xor_sync(0xffffffffu, p[j], 2);
        }
        __syncthreads();
        if (tig == 0) {
#pragma unroll
            for (int j = 0; j < 4; j++) {
                int rr = wm * 32 + (j >> 1) * 16 + (j & 1) * 8 + g;
                atomicAdd(&sVel[rr], p[j]);
            }
        }
        __syncthreads();
        if (t < 64) {
            int n = n0 + t;
            if (n < NN) out[n] = sVel[t] + bv2[0];
        }
    }
}

// ---------------- edge kernel: 64 edges/CTA, 3 CTAs/SM --------------------
#define OFF_AH 0u          // 17408
#define OFF_AL 17408u      // 17408
#define OFF_X  34816u      // misc 4352
#define SMEM_EDGE_TOTAL 39168

__global__ __launch_bounds__(256, 3) void edge_kernel_mma(
    const float* __restrict__ coord_diff,
    const int* __restrict__ row, const int* __restrict__ col,
    const float* __restrict__ We1, const float* __restrict__ be1,
    const float* __restrict__ be2,
    const float* __restrict__ bc1, const float* __restrict__ Wc2)
{
    extern __shared__ __align__(16) char smem[];
    unsigned short* sAh = (unsigned short*)(smem + OFF_AH);
    unsigned short* sAl = (unsigned short*)(smem + OFF_AL);
    int*   sRow  = (int*)  (smem + OFF_X);
    int*   sCol  = (int*)  (smem + OFF_X + 256);
    float* sRad  = (float*)(smem + OFF_X + 512);
    float* sCD   = (float*)(smem + OFF_X + 768);
    float* sBe1  = (float*)(smem + OFF_X + 1536);
    float* sW256 = (float*)(smem + OFF_X + 2048);
    float* sBe2  = (float*)(smem + OFF_X + 2560);
    float* sBc1  = (float*)(smem + OFF_X + 3072);
    float* sWc2  = (float*)(smem + OFF_X + 3584);
    float* sCoef = (float*)(smem + OFF_X + 4096);

    const int t    = threadIdx.x;
    const int lane = t & 31;
    const int wid  = t >> 5;
    const int wm   = wid >> 2;
    const int wn   = wid & 3;
    const int g    = lane >> 2;
    const int tig  = lane & 3;
    const int e0   = blockIdx.x * 64;

    if (t < 64) {
        int e = e0 + t;
        sRow[t] = row[e];
        sCol[t] = col[e];
        float cx = coord_diff[e * 3 + 0];
        float cy = coord_diff[e * 3 + 1];
        float cz = coord_diff[e * 3 + 2];
        sCD[t * 3 + 0] = cx; sCD[t * 3 + 1] = cy; sCD[t * 3 + 2] = cz;
        sRad[t] = cx * cx + cy * cy + cz * cz;
        sCoef[t] = 0.0f;
    }
    if (t < 128) {
        sBe1[t]  = be1[t];
        sW256[t] = We1[256 * 128 + t];
        sBe2[t]  = be2[t];
        sBc1[t]  = bc1[t];
        sWc2[t]  = Wc2[t];
    }
    __syncthreads();

    // ---- h1 = silu(P1[row] + P2[col] + rad*w256 + be1) -> A (K=128) ----
    for (int i = t; i < 64 * 32; i += 256) {
        int e = i >> 5;
        int k = (i & 31) * 4;
        float rad = sRad[e];
        float4 a = *(const float4*)(g_P1 + (size_t)sRow[e] * 128 + k);
        float4 b = *(const float4*)(g_P2 + (size_t)sCol[e] * 128 + k);
        float4 w = *(const float4*)(sW256 + k);
        float4 bb = *(const float4*)(sBe1 + k);
        float x0 = silu_f(a.x + b.x + rad * w.x + bb.x);
        float x1 = silu_f(a.y + b.y + rad * w.y + bb.y);
        float x2 = silu_f(a.z + b.z + rad * w.z + bb.z);
        float x3 = silu_f(a.w + b.w + rad * w.w + bb.w);
        uint32_t h0, l0, h1, l1;
        split_pack(x0, x1, h0, l0);
        split_pack(x2, x3, h1, l1);
        *(uint2*)(sAh + e * SAS + k) = make_uint2(h0, h1);
        *(uint2*)(sAl + e * SAS + k) = make_uint2(l0, l1);
    }
    __syncthreads();

    float acc[2][4][4];

    // ---- GEMM2: m = silu(h1 @ We2 + be2), K=128 ----
#pragma unroll
    for (int a = 0; a < 2; a++)
#pragma unroll
        for (int b = 0; b < 4; b++)
#pragma unroll
            for (int c = 0; c < 4; c++) acc[a][b][c] = 0.0f;
    gemm_tiles(sAh, sAl, g_We2f, 8, 0, 8, wm, wn, lane, acc);
    __syncthreads();

    // ---- epilogue2: m = silu(D+be2); RED to g_agg from regs; bf16 -> A ----
#pragma unroll
    for (int mi = 0; mi < 2; mi++) {
        int rA = wm * 32 + mi * 16 + g;
        int rB = rA + 8;
        int rowA = sRow[rA], rowB = sRow[rB];
#pragma unroll
        for (int ni = 0; ni < 4; ni++) {
            int cb = wn * 32 + ni * 8 + tig * 2;
            float b0 = sBe2[cb], b1 = sBe2[cb + 1];
            float m0 = silu_f(acc[mi][ni][0] + b0);
            float m1 = silu_f(acc[mi][ni][1] + b1);
            float m2 = silu_f(acc[mi][ni][2] + b0);
            float m3 = silu_f(acc[mi][ni][3] + b1);
            red_add_v2(&g_agg[(size_t)rowA * 128 + cb], m0, m1);
            red_add_v2(&g_agg[(size_t)rowB * 128 + cb], m2, m3);
            uint32_t hi, lo;
            split_pack(m0, m1, hi, lo);
            *(uint32_t*)(sAh + rA * SAS + cb) = hi;
            *(uint32_t*)(sAl + rA * SAS + cb) = lo;
            split_pack(m2, m3, hi, lo);
            *(uint32_t*)(sAh + rB * SAS + cb) = hi;
            *(uint32_t*)(sAl + rB * SAS + cb) = lo;
        }
    }
    __syncthreads();

    // ---- GEMM3: K=128 ----
#pragma unroll
    for (int a = 0; a < 2; a++)
#pragma unroll
        for (int b = 0; b < 4; b++)
#pragma unroll
            for (int c = 0; c < 4; c++) acc[a][b][c] = 0.0f;
    gemm_tiles(sAh, sAl, g_Wc1f, 8, 0, 8, wm, wn, lane, acc);

    // ---- epilogue3: coef = sum_n silu(D + bc1) * Wc2 ----
    {
        float p[4] = {0.f, 0.f, 0.f, 0.f};
#pragma unroll
        for (int ni = 0; ni < 4; ni++) {
            int cb = wn * 32 + ni * 8 + tig * 2;
            float b0 = sBc1[cb], b1 = sBc1[cb + 1];
            float w0 = sWc2[cb], w1 = sWc2[cb + 1];
#pragma unroll
            for (int mi = 0; mi < 2; mi++) {
                p[mi * 2 + 0] += silu_f(acc[mi][ni][0] + b0) * w0
                               + silu_f(acc[mi][ni][1] + b1) * w1;
                p[mi * 2 + 1] += silu_f(acc[mi][ni][2] + b0) * w0
                               + silu_f(acc[mi][ni][3] + b1) * w1;
            }
        }
#pragma unroll
        for (int j = 0; j < 4; j++) {
            p[j] += __shfl_xor_sync(0xffffffffu, p[j], 1);
            p[j] += __shfl_xor_sync(0xffffffffu, p[j], 2);
        }
        if (tig == 0) {
#pragma unroll
            for (int j = 0; j < 4; j++) {
                int rr = wm * 32 + (j >> 1) * 16 + (j & 1) * 8 + g;
                atomicAdd(&sCoef[rr], p[j]);
            }
        }
    }
    __syncthreads();

    // ---- force scatter ----
    if (t < 64) {
        int r = sRow[t];
        float c = sCoef[t];
#pragma unroll
        for (int q = 0; q < 3; q++) {
            float v = sCD[t * 3 + q] * c;
            v = fminf(fmaxf(v, -100.0f), 100.0f);
            atomicAdd(&g_fsum[r * 3 + q], v);
        }
        atomicAdd(&g_cnt[r], 1.0f);
    }
}

// ---------------------------------------------------------------------------
// Node kernel (mma): h_out = silu(Q1 + agg@Wn1_bot) @ Wn2 + bn2 ; normalize
// out layout: [vel (N)] [force (N*3)] [h_out (N*128)]
// ---------------------------------------------------------------------------
#define NOFF_X 34816u
#define SMEM_NODE_TOTAL 35840

__global__ __launch_bounds__(256, 3) void node_kernel_mma(
    const float* __restrict__ bn2,
    float* __restrict__ out)
{
    extern __shared__ __align__(16) char smem[];
    unsigned short* sAh = (unsigned short*)smem;
    unsigned short* sAl = (unsigned short*)(smem + 17408);
    float* sBn2 = (float*)(smem + NOFF_X);   // 512B

    const int t    = threadIdx.x;
    const int lane = t & 31;
    const int wid  = t >> 5;
    const int wm   = wid >> 2;
    const int wn   = wid & 3;
    const int g    = lane >> 2;
    const int tig  = lane & 3;
    const int n0   = blockIdx.x * 64;

    if (t < 128) sBn2[t] = bn2[t];

    // ---- gather agg rows -> split -> A ----
    for (int i = t; i < 64 * 32; i += 256) {
        int e = i >> 5;
        int k = (i & 31) * 4;
        int n = n0 + e;
        float4 v = make_float4(0.f, 0.f, 0.f, 0.f);
        if (n < NN) v = *(const float4*)(g_agg + (size_t)n * 128 + k);
        uint32_t h0, l0, h1, l1;
        split_pack(v.x, v.y, h0, l0);
        split_pack(v.z, v.w, h1, l1);
        *(uint2*)(sAh + e * SAS + k) = make_uint2(h0, h1);
        *(uint2*)(sAl + e * SAS + k) = make_uint2(l0, l1);
    }
    __syncthreads();

    float acc[2][4][4];

    // ---- GEMM1: agg @ Wn1_bot ----
#pragma unroll
    for (int a = 0; a < 2; a++)
#pragma unroll
        for (int b = 0; b < 4; b++)
#pragma unroll
            for (int c = 0; c < 4; c++) acc[a][b][c] = 0.0f;
    gemm_tiles(sAh, sAl, g_Wn1bf, 8, 0, 8, wm, wn, lane, acc);
    __syncthreads();

    // ---- epilogue1: x = silu(acc + Q1) -> A ----
#pragma unroll
    for (int mi = 0; mi < 2; mi++) {
        int rA = wm * 32 + mi * 16 + g;
        int rB = rA + 8;
        int nA = n0 + rA, nB = n0 + rB;
#pragma unroll
        for (int ni = 0; ni < 4; ni++) {
            int cb = wn * 32 + ni * 8 + tig * 2;
            float q0 = 0.f, q1 = 0.f, q2 = 0.f, q3 = 0.f;
            if (nA < NN) {
                float2 q = *(const float2*)(g_Q1 + (size_t)nA * 128 + cb);
                q0 = q.x; q1 = q.y;
            }
            if (nB < NN) {
                float2 q = *(const float2*)(g_Q1 + (size_t)nB * 128 + cb);
                q2 = q.x; q3 = q.y;
            }
            float x0 = silu_f(acc[mi][ni][0] + q0);
            float x1 = silu_f(acc[mi][ni][1] + q1);
            float x2 = silu_f(acc[mi][ni][2] + q2);
            float x3 = silu_f(acc[mi][ni][3] + q3);
            uint32_t hi, lo;
            split_pack(x0, x1, hi, lo);
            *(uint32_t*)(sAh + rA * SAS + cb) = hi;
            *(uint32_t*)(sAl + rA * SAS + cb) = lo;
            split_pack(x2, x3, hi, lo);
            *(uint32_t*)(sAh + rB * SAS + cb) = hi;
            *(uint32_t*)(sAl + rB * SAS + cb) = lo;
        }
    }
    __syncthreads();

    // ---- GEMM2: h_out = x @ Wn2 + bn2 ----
#pragma unroll
    for (int a = 0; a < 2; a++)
#pragma unroll
        for (int b = 0; b < 4; b++)
#pragma unroll
            for (int c = 0; c < 4; c++) acc[a][b][c] = 0.0f;
    gemm_tiles(sAh, sAl, g_Wn2f, 8, 0, 8, wm, wn, lane, acc);

    {
        float* outH = out + (size_t)4 * NN;
#pragma unroll
        for (int mi = 0; mi < 2; mi++) {
            int rA = wm * 32 + mi * 16 + g;
            int rB = rA + 8;
            int nA = n0 + rA, nB = n0 + rB;
#pragma unroll
            for (int ni = 0; ni < 4; ni++) {
                int cb = wn * 32 + ni * 8 + tig * 2;
                float b0 = sBn2[cb], b1 = sBn2[cb + 1];
                if (nA < NN) {
                    float2 v; v.x = acc[mi][ni][0] + b0; v.y = acc[mi][ni][1] + b1;
                    *(float2*)(outH + (size_t)nA * 128 + cb) = v;
                }
                if (nB < NN) {
                    float2 v; v.x = acc[mi][ni][2] + b0; v.y = acc[mi][ni][3] + b1;
                    *(float2*)(outH + (size_t)nB * 128 + cb) = v;
                }
            }
        }
    }

    // ---- force normalize ----
    if (t < 64) {
        int n = n0 + t;
        if (n < NN) {
            float c = g_cnt[n];
            float inv = 1.0f / fmaxf(c, 1.0f);
            out[NN + (size_t)n * 3 + 0] = g_fsum[n * 3 + 0] * inv;
            out[NN + (size_t)n * 3 + 1] = g_fsum[n * 3 + 1] * inv;
            out[NN + (size_t)n * 3 + 2] = g_fsum[n * 3 + 2] * inv;
        }
    }
}

// ---------------------------------------------------------------------------
extern "C" void kernel_launch(void* const* d_in, const int* in_sizes, int n_in,
                              void* d_out, int out_size)
{
    const float* h          = (const float*)d_in[0];
    const float* coord_diff = (const float*)d_in[1];
    const int*   row        = (const int*)  d_in[2];
    const int*   col        = (const int*)  d_in[3];
    const float* We1 = (const float*)d_in[4];
    const float* be1 = (const float*)d_in[5];
    const float* We2 = (const float*)d_in[6];
    const float* be2 = (const float*)d_in[7];
    const float* Wn1 = (const float*)d_in[8];
    const float* bn1 = (const float*)d_in[9];
    const float* Wn2 = (const float*)d_in[10];
    const float* bn2 = (const float*)d_in[11];
    const float* Wc1 = (const float*)d_in[12];
    const float* bc1 = (const float*)d_in[13];
    const float* Wc2 = (const float*)d_in[14];
    const float* Wv1 = (const float*)d_in[15];
    const float* bv1 = (const float*)d_in[16];
    const float* Wv2 = (const float*)d_in[17];
    const float* bv2 = (const float*)d_in[18];
    float* out = (float*)d_out;

    void *aggp, *fsump, *cntp;
    cudaGetSymbolAddress(&aggp, g_agg);
    cudaGetSymbolAddress(&fsump, g_fsum);
    cudaGetSymbolAddress(&cntp, g_cnt);
    cudaMemsetAsync(aggp,  0, (size_t)NN * 128 * sizeof(float));
    cudaMemsetAsync(fsump, 0, (size_t)NN * 3 * sizeof(float));
    cudaMemsetAsync(cntp,  0, (size_t)NN * sizeof(float));

    prep_weights_f<<<512, 256>>>(We1, We2, Wc1, Wn1, Wv1, Wn2);

    precompute_p<<<(NN + 63) / 64, 256, 36864>>>(h, bn1, bv1, Wv2, bv2, out);

    cudaFuncSetAttribute(edge_kernel_mma, cudaFuncAttributeMaxDynamicSharedMemorySize,
                         SMEM_EDGE_TOTAL);
    edge_kernel_mma<<<EE / 64, 256, SMEM_EDGE_TOTAL>>>(
        coord_diff, row, col, We1, be1, be2, bc1, Wc2);

    cudaFuncSetAttribute(node_kernel_mma, cudaFuncAttributeMaxDynamicSharedMemorySize,
                         SMEM_NODE_TOTAL);
    node_kernel_mma<<<(NN + 63) / 64, 256, SMEM_NODE_TOTAL>>>(bn2, out);
}

// round 14
// speedup vs baseline: 1.8236x; 1.0966x over previous
#include <cuda_runtime.h>
#include <cuda_bf16.h>
#include <cstdint>

#define NN 50000
#define EE 800000

// ---------------- scratch (__device__ globals; no allocs) ----------------
__device__ float g_agg[(size_t)NN * 128];
__device__ float g_fsum[NN * 3];
__device__ float g_cnt[NN];
__device__ float g_P1[(size_t)NN * 128];   // h @ We1[0:128,:]
__device__ float g_P2[(size_t)NN * 128];   // h @ We1[128:256,:]
__device__ float g_Q1[(size_t)NN * 128];   // h @ Wn1[0:128,:] + bn1

// tf32 fragments (m16n8k8): uint2 per lane = {W[k][n], W[k+4][n]},
//   index (nt*KT + kt)*32 + lane ; n = nt*8 + lane/4 ; k = kt*8 + lane%4
__device__ __align__(16) uint2 g_We1f[16384];  // K=256, KT=32
__device__ __align__(16) uint2 g_We2f[8192];   // K=128, KT=16
__device__ __align__(16) uint2 g_Wc1f[8192];   // K=128
__device__ __align__(16) uint2 g_Wn1tf[8192];  // Wn1 top, K=128
__device__ __align__(16) uint2 g_Wv1f[8192];   // Wv1, K=128
// bf16 hi/lo fragments (m16n8k16) for node kernel (kept high-precision)
__device__ __align__(16) uint2 g_Wn1bf[8192];  // Wn1 bottom
__device__ __align__(16) uint2 g_Wn2f[8192];   // Wn2

__device__ __forceinline__ float silu_f(float x) {
    return x / (1.0f + __expf(-x));
}
__device__ __forceinline__ uint32_t to_tf32(float x) {
    uint32_t r; asm("cvt.rna.tf32.f32 %0, %1;" : "=r"(r) : "f"(x)); return r;
}
__device__ __forceinline__ void split_pack(float f0, float f1, uint32_t& hi, uint32_t& lo) {
    __nv_bfloat162 bh = __floats2bfloat162_rn(f0, f1);
    float2 bf = __bfloat1622float2(bh);
    __nv_bfloat162 bl = __floats2bfloat162_rn(f0 - bf.x, f1 - bf.y);
    hi = *(uint32_t*)&bh;
    lo = *(uint32_t*)&bl;
}
__device__ __forceinline__ void mma16816(float* c, const uint32_t* a, const uint32_t* b) {
    asm volatile(
        "mma.sync.aligned.m16n8k16.row.col.f32.bf16.bf16.f32 "
        "{%0,%1,%2,%3}, {%4,%5,%6,%7}, {%8,%9}, {%0,%1,%2,%3};"
        : "+f"(c[0]), "+f"(c[1]), "+f"(c[2]), "+f"(c[3])
        : "r"(a[0]), "r"(a[1]), "r"(a[2]), "r"(a[3]), "r"(b[0]), "r"(b[1]));
}
__device__ __forceinline__ void mma1688(float* c, const uint32_t* a, const uint32_t* b) {
    asm volatile(
        "mma.sync.aligned.m16n8k8.row.col.f32.tf32.tf32.f32 "
        "{%0,%1,%2,%3}, {%4,%5,%6,%7}, {%8,%9}, {%0,%1,%2,%3};"
        : "+f"(c[0]), "+f"(c[1]), "+f"(c[2]), "+f"(c[3])
        : "r"(a[0]), "r"(a[1]), "r"(a[2]), "r"(a[3]), "r"(b[0]), "r"(b[1]));
}
__device__ __forceinline__ void red_add_v2(float* gptr, float a, float b) {
    asm volatile("red.global.add.v2.f32 [%0], {%1, %2};"
                 :: "l"(gptr), "f"(a), "f"(b) : "memory");
}
__device__ __forceinline__ void ldsm4(uint32_t* r, uint32_t saddr) {
    asm volatile("ldmatrix.sync.aligned.m8n8.x4.shared.b16 {%0,%1,%2,%3}, [%4];"
                 : "=r"(r[0]), "=r"(r[1]), "=r"(r[2]), "=r"(r[3]) : "r"(saddr));
}

#define SAS4 132   // tf32 A stride (u32) -> 528B rows, conflict-free ldsm
#define SASB 136   // bf16 A stride (b16) for node kernel

// ---------------- prep: weights -> fragments ------------------------------
__global__ void prep_weights_f(const float* __restrict__ We1,
                               const float* __restrict__ We2,
                               const float* __restrict__ Wc1,
                               const float* __restrict__ Wn1,
                               const float* __restrict__ Wv1,
                               const float* __restrict__ Wn2) {
    int i = blockIdx.x * blockDim.x + threadIdx.x;
    if (i < 49152) {
        const float* W; uint2* out; int KT, j;
        if (i < 16384)      { W = We1; out = g_We1f;  KT = 32; j = i; }
        else if (i < 24576) { W = We2; out = g_We2f;  KT = 16; j = i - 16384; }
        else if (i < 32768) { W = Wc1; out = g_Wc1f;  KT = 16; j = i - 24576; }
        else if (i < 40960) { W = Wn1; out = g_Wn1tf; KT = 16; j = i - 32768; }
        else                { W = Wv1; out = g_Wv1f;  KT = 16; j = i - 40960; }
        int nt = j / (KT * 32); int rem = j % (KT * 32);
        int kt = rem >> 5; int lane = rem & 31;
        int g = lane >> 2, tig = lane & 3;
        int n = nt * 8 + g;
        int k = kt * 8 + tig;
        uint2 v;
        v.x = to_tf32(W[k * 128 + n]);
        v.y = to_tf32(W[(k + 4) * 128 + n]);
        out[(nt * KT + kt) * 32 + lane] = v;
    } else if (i < 81920) {
        int j = i - 49152;
        const float* W; uint32_t* out;
        if (j < 16384) { W = Wn1 + 128 * 128; out = (uint32_t*)g_Wn1bf; }
        else           { W = Wn2;             out = (uint32_t*)g_Wn2f; j -= 16384; }
        const int KT = 8;
        int per_hl = 16 * KT * 64;
        int hl = j / per_hl; int rem = j % per_hl;
        int nt = rem / (KT * 64); rem %= KT * 64;
        int kt = rem / 64; rem %= 64;
        int lane = rem >> 1, r = rem & 1;
        int g = lane >> 2, tig = lane & 3;
        int n = nt * 8 + g;
        int k = kt * 16 + tig * 2 + r * 8;
        float w0 = W[k * 128 + n], w1 = W[(k + 1) * 128 + n];
        __nv_bfloat162 p;
        if (hl == 0) {
            p.x = __float2bfloat16(w0);
            p.y = __float2bfloat16(w1);
        } else {
            __nv_bfloat16 h0 = __float2bfloat16(w0), h1 = __float2bfloat16(w1);
            p.x = __float2bfloat16(w0 - __bfloat162float(h0));
            p.y = __float2bfloat16(w1 - __bfloat162float(h1));
        }
        out[((hl * 16 + nt) * KT + kt) * 64 + lane * 2 + r] = *(uint32_t*)&p;
    }
}

// ---------------- tf32 GEMM core: 2x4 mma tiles per warp, ldsm A ----------
__device__ __forceinline__ void gemm_tf32(
    const uint32_t* sA, const uint2* __restrict__ Bf, int KTtot, int kt0, int ktn,
    int wm, int wn, int lane, float acc[2][4][4])
{
    const int m0 = wm * 32;
    const int rsel = lane & 15;
    const int csel = ((lane >> 4) & 1) * 4;
    const uint32_t b0 = (uint32_t)__cvta_generic_to_shared(sA + (m0 + rsel) * SAS4 + csel);
    const uint32_t b1 = (uint32_t)__cvta_generic_to_shared(sA + (m0 + 16 + rsel) * SAS4 + csel);
    for (int kti = 0; kti < ktn; kti++) {
        uint32_t a0[4], a1[4];
        const uint32_t koff = (uint32_t)kti * 32;   // 8 tf32 = 32B
        ldsm4(a0, b0 + koff);
        ldsm4(a1, b1 + koff);
        const int kt = kt0 + kti;
#pragma unroll
        for (int ni = 0; ni < 4; ni++) {
            const int nt = wn * 4 + ni;
            uint2 bv = Bf[(nt * KTtot + kt) * 32 + lane];
            uint32_t br[2] = {bv.x, bv.y};
            mma1688(acc[0][ni], a0, br);
            mma1688(acc[1][ni], a1, br);
        }
    }
}

// ---------------- bf16 GEMM core (node kernel) ----------------------------
__device__ __forceinline__ void gemm_bf16(
    const unsigned short* sAh, const unsigned short* sAl,
    const uint2* __restrict__ Bf, int KTtot, int kt0, int ktn,
    int wm, int wn, int lane, float acc[2][4][4])
{
    const int m0 = wm * 32;
    const int rsel = lane & 15;
    const int csel = ((lane >> 4) & 1) * 8;
    const uint32_t bH0 = (uint32_t)__cvta_generic_to_shared(sAh + (m0 + rsel) * SASB + csel);
    const uint32_t bH1 = (uint32_t)__cvta_generic_to_shared(sAh + (m0 + 16 + rsel) * SASB + csel);
    const uint32_t bL0 = (uint32_t)__cvta_generic_to_shared(sAl + (m0 + rsel) * SASB + csel);
    const uint32_t bL1 = (uint32_t)__cvta_generic_to_shared(sAl + (m0 + 16 + rsel) * SASB + csel);
    for (int kti = 0; kti < ktn; kti++) {
        uint32_t ah[2][4], al[2][4];
        const uint32_t koff = (uint32_t)kti * 32;
        ldsm4(ah[0], bH0 + koff);
        ldsm4(ah[1], bH1 + koff);
        ldsm4(al[0], bL0 + koff);
        ldsm4(al[1], bL1 + koff);
        const int kt = kt0 + kti;
#pragma unroll
        for (int ni = 0; ni < 4; ni++) {
            const int nt = wn * 4 + ni;
            uint2 bh = Bf[(nt * KTtot + kt) * 32 + lane];
            uint2 bl = Bf[((16 + nt) * KTtot + kt) * 32 + lane];
            uint32_t bhr[2] = {bh.x, bh.y};
            uint32_t blr[2] = {bl.x, bl.y};
            mma16816(acc[0][ni], ah[0], bhr);
            mma16816(acc[1][ni], ah[1], bhr);
            mma16816(acc[0][ni], al[0], bhr);
            mma16816(acc[1][ni], al[1], bhr);
            mma16816(acc[0][ni], ah[0], blr);
            mma16816(acc[1][ni], ah[1], blr);
        }
    }
}

// ---------------- precompute: P1, P2, Q1, vel (tf32) ----------------------
// smem: sA [0,33792) u32, sBn1 33792, sBv1 34304, sWv2 34816, sVel 35328
#define SMEM_PRE_TOTAL 35584

__global__ __launch_bounds__(256, 3) void precompute_p(
    const float* __restrict__ h,
    const float* __restrict__ bn1,
    const float* __restrict__ bv1,
    const float* __restrict__ Wv2, const float* __restrict__ bv2,
    float* __restrict__ out)
{
    extern __shared__ __align__(16) char smem[];
    uint32_t* sA = (uint32_t*)smem;
    float* sBn1 = (float*)(smem + 33792);
    float* sBv1 = (float*)(smem + 34304);
    float* sWv2 = (float*)(smem + 34816);
    float* sVel = (float*)(smem + 35328);

    const int t    = threadIdx.x;
    const int lane = t & 31;
    const int wid  = t >> 5;
    const int wm   = wid >> 2;
    const int wn   = wid & 3;
    const int g    = lane >> 2;
    const int tig  = lane & 3;
    const int n0   = blockIdx.x * 64;

    if (t < 128) {
        sBn1[t] = bn1[t];
        sBv1[t] = bv1[t];
        sWv2[t] = Wv2[t];
    }
    if (t < 64) sVel[t] = 0.0f;

    for (int i = t; i < 64 * 32; i += 256) {
        int e = i >> 5;
        int k = (i & 31) * 4;
        int n = n0 + e;
        float4 v = make_float4(0.f, 0.f, 0.f, 0.f);
        if (n < NN) v = *(const float4*)(h + (size_t)n * 128 + k);
        uint4 o;
        o.x = to_tf32(v.x); o.y = to_tf32(v.y);
        o.z = to_tf32(v.z); o.w = to_tf32(v.w);
        *(uint4*)(sA + e * SAS4 + k) = o;
    }
    __syncthreads();

    float acc[2][4][4];

    // ---- P1, P2 (We1 halves, KTtot=32) ----
#pragma unroll
    for (int p = 0; p < 2; p++) {
#pragma unroll
        for (int a = 0; a < 2; a++)
#pragma unroll
            for (int b = 0; b < 4; b++)
#pragma unroll
                for (int c = 0; c < 4; c++) acc[a][b][c] = 0.0f;
        gemm_tf32(sA, g_We1f, 32, p * 16, 16, wm, wn, lane, acc);
        float* outp = p ? g_P2 : g_P1;
#pragma unroll
        for (int mi = 0; mi < 2; mi++) {
            int rA = n0 + wm * 32 + mi * 16 + g;
            int rB = rA + 8;
#pragma unroll
            for (int ni = 0; ni < 4; ni++) {
                int cb = wn * 32 + ni * 8 + tig * 2;
                if (rA < NN) {
                    outp[(size_t)rA * 128 + cb]     = acc[mi][ni][0];
                    outp[(size_t)rA * 128 + cb + 1] = acc[mi][ni][1];
                }
                if (rB < NN) {
                    outp[(size_t)rB * 128 + cb]     = acc[mi][ni][2];
                    outp[(size_t)rB * 128 + cb + 1] = acc[mi][ni][3];
                }
            }
        }
    }

    // ---- Q1 = h @ Wn1_top + bn1 ----
    {
#pragma unroll
        for (int a = 0; a < 2; a++)
#pragma unroll
            for (int b = 0; b < 4; b++)
#pragma unroll
                for (int c = 0; c < 4; c++) acc[a][b][c] = 0.0f;
        gemm_tf32(sA, g_Wn1tf, 16, 0, 16, wm, wn, lane, acc);
#pragma unroll
        for (int mi = 0; mi < 2; mi++) {
            int rA = n0 + wm * 32 + mi * 16 + g;
            int rB = rA + 8;
#pragma unroll
            for (int ni = 0; ni < 4; ni++) {
                int cb = wn * 32 + ni * 8 + tig * 2;
                float b0 = sBn1[cb], b1 = sBn1[cb + 1];
                if (rA < NN) {
                    g_Q1[(size_t)rA * 128 + cb]     = acc[mi][ni][0] + b0;
                    g_Q1[(size_t)rA * 128 + cb + 1] = acc[mi][ni][1] + b1;
                }
                if (rB < NN) {
                    g_Q1[(size_t)rB * 128 + cb]     = acc[mi][ni][2] + b0;
                    g_Q1[(size_t)rB * 128 + cb + 1] = acc[mi][ni][3] + b1;
                }
            }
        }
    }

    // ---- vel = silu(h @ Wv1 + bv1) @ Wv2 + bv2 -> out[0..NN) ----
    {
#pragma unroll
        for (int a = 0; a < 2; a++)
#pragma unroll
            for (int b = 0; b < 4; b++)
#pragma unroll
                for (int c = 0; c < 4; c++) acc[a][b][c] = 0.0f;
        gemm_tf32(sA, g_Wv1f, 16, 0, 16, wm, wn, lane, acc);
        float p[4] = {0.f, 0.f, 0.f, 0.f};
#pragma unroll
        for (int ni = 0; ni < 4; ni++) {
            int cb = wn * 32 + ni * 8 + tig * 2;
            float b0 = sBv1[cb], b1 = sBv1[cb + 1];
            float w0 = sWv2[cb], w1 = sWv2[cb + 1];
#pragma unroll
            for (int mi = 0; mi < 2; mi++) {
                p[mi * 2 + 0] += silu_f(acc[mi][ni][0] + b0) * w0
                               + silu_f(acc[mi][ni][1] + b1) * w1;
                p[mi * 2 + 1] += silu_f(acc[mi][ni][2] + b0) * w0
                               + silu_f(acc[mi][ni][3] + b1) * w1;
            }
        }
#pragma unroll
        for (int j = 0; j < 4; j++) {
            p[j] += __shfl_xor_sync(0xffffffffu, p[j], 1);
            p[j] += __shfl_xor_sync(0xffffffffu, p[j], 2);
        }
        __syncthreads();
        if (tig == 0) {
#pragma unroll
            for (int j = 0; j < 4; j++) {
                int rr = wm * 32 + (j >> 1) * 16 + (j & 1) * 8 + g;
                atomicAdd(&sVel[rr], p[j]);
            }
        }
        __syncthreads();
        if (t < 64) {
            int n = n0 + t;
            if (n < NN) out[n] = sVel[t] + bv2[0];
        }
    }
}

// ---------------- edge kernel: 64 edges/CTA, tf32, 3 CTAs/SM --------------
#define EOFF_X 33792u
#define SMEM_EDGE_TOTAL 38144

__global__ __launch_bounds__(256, 3) void edge_kernel_mma(
    const float* __restrict__ coord_diff,
    const int* __restrict__ row, const int* __restrict__ col,
    const float* __restrict__ We1, const float* __restrict__ be1,
    const float* __restrict__ be2,
    const float* __restrict__ bc1, const float* __restrict__ Wc2)
{
    extern __shared__ __align__(16) char smem[];
    uint32_t* sA = (uint32_t*)smem;
    int*   sRow  = (int*)  (smem + EOFF_X);
    int*   sCol  = (int*)  (smem + EOFF_X + 256);
    float* sRad  = (float*)(smem + EOFF_X + 512);
    float* sCD   = (float*)(smem + EOFF_X + 768);
    float* sBe1  = (float*)(smem + EOFF_X + 1536);
    float* sW256 = (float*)(smem + EOFF_X + 2048);
    float* sBe2  = (float*)(smem + EOFF_X + 2560);
    float* sBc1  = (float*)(smem + EOFF_X + 3072);
    float* sWc2  = (float*)(smem + EOFF_X + 3584);
    float* sCoef = (float*)(smem + EOFF_X + 4096);

    const int t    = threadIdx.x;
    const int lane = t & 31;
    const int wid  = t >> 5;
    const int wm   = wid >> 2;
    const int wn   = wid & 3;
    const int g    = lane >> 2;
    const int tig  = lane & 3;
    const int e0   = blockIdx.x * 64;

    if (t < 64) {
        int e = e0 + t;
        sRow[t] = row[e];
        sCol[t] = col[e];
        float cx = coord_diff[e * 3 + 0];
        float cy = coord_diff[e * 3 + 1];
        float cz = coord_diff[e * 3 + 2];
        sCD[t * 3 + 0] = cx; sCD[t * 3 + 1] = cy; sCD[t * 3 + 2] = cz;
        sRad[t] = cx * cx + cy * cy + cz * cz;
        sCoef[t] = 0.0f;
    }
    if (t < 128) {
        sBe1[t]  = be1[t];
        sW256[t] = We1[256 * 128 + t];
        sBe2[t]  = be2[t];
        sBc1[t]  = bc1[t];
        sWc2[t]  = Wc2[t];
    }
    __syncthreads();

    // ---- h1 = silu(P1[row] + P2[col] + rad*w256 + be1) -> A tf32 ----
    for (int i = t; i < 64 * 32; i += 256) {
        int e = i >> 5;
        int k = (i & 31) * 4;
        float rad = sRad[e];
        float4 a = *(const float4*)(g_P1 + (size_t)sRow[e] * 128 + k);
        float4 b = *(const float4*)(g_P2 + (size_t)sCol[e] * 128 + k);
        float4 w = *(const float4*)(sW256 + k);
        float4 bb = *(const float4*)(sBe1 + k);
        uint4 o;
        o.x = to_tf32(silu_f(a.x + b.x + rad * w.x + bb.x));
        o.y = to_tf32(silu_f(a.y + b.y + rad * w.y + bb.y));
        o.z = to_tf32(silu_f(a.z + b.z + rad * w.z + bb.z));
        o.w = to_tf32(silu_f(a.w + b.w + rad * w.w + bb.w));
        *(uint4*)(sA + e * SAS4 + k) = o;
    }
    __syncthreads();

    float acc[2][4][4];

    // ---- GEMM2: m = silu(h1 @ We2 + be2), K=128 ----
#pragma unroll
    for (int a = 0; a < 2; a++)
#pragma unroll
        for (int b = 0; b < 4; b++)
#pragma unroll
            for (int c = 0; c < 4; c++) acc[a][b][c] = 0.0f;
    gemm_tf32(sA, g_We2f, 16, 0, 16, wm, wn, lane, acc);
    __syncthreads();

    // ---- epilogue2: m = silu(D+be2); RED to g_agg; tf32 -> A ----
#pragma unroll
    for (int mi = 0; mi < 2; mi++) {
        int rA = wm * 32 + mi * 16 + g;
        int rB = rA + 8;
        int rowA = sRow[rA], rowB = sRow[rB];
#pragma unroll
        for (int ni = 0; ni < 4; ni++) {
            int cb = wn * 32 + ni * 8 + tig * 2;
            float b0 = sBe2[cb], b1 = sBe2[cb + 1];
            float m0 = silu_f(acc[mi][ni][0] + b0);
            float m1 = silu_f(acc[mi][ni][1] + b1);
            float m2 = silu_f(acc[mi][ni][2] + b0);
            float m3 = silu_f(acc[mi][ni][3] + b1);
            red_add_v2(&g_agg[(size_t)rowA * 128 + cb], m0, m1);
            red_add_v2(&g_agg[(size_t)rowB * 128 + cb], m2, m3);
            uint2 pa; pa.x = to_tf32(m0); pa.y = to_tf32(m1);
            *(uint2*)(sA + rA * SAS4 + cb) = pa;
            uint2 pb; pb.x = to_tf32(m2); pb.y = to_tf32(m3);
            *(uint2*)(sA + rB * SAS4 + cb) = pb;
        }
    }
    __syncthreads();

    // ---- GEMM3: K=128 ----
#pragma unroll
    for (int a = 0; a < 2; a++)
#pragma unroll
        for (int b = 0; b < 4; b++)
#pragma unroll
            for (int c = 0; c < 4; c++) acc[a][b][c] = 0.0f;
    gemm_tf32(sA, g_Wc1f, 16, 0, 16, wm, wn, lane, acc);

    // ---- epilogue3: coef = sum_n silu(D + bc1) * Wc2 ----
    {
        float p[4] = {0.f, 0.f, 0.f, 0.f};
#pragma unroll
        for (int ni = 0; ni < 4; ni++) {
            int cb = wn * 32 + ni * 8 + tig * 2;
            float b0 = sBc1[cb], b1 = sBc1[cb + 1];
            float w0 = sWc2[cb], w1 = sWc2[cb + 1];
#pragma unroll
            for (int mi = 0; mi < 2; mi++) {
                p[mi * 2 + 0] += silu_f(acc[mi][ni][0] + b0) * w0
                               + silu_f(acc[mi][ni][1] + b1) * w1;
                p[mi * 2 + 1] += silu_f(acc[mi][ni][2] + b0) * w0
                               + silu_f(acc[mi][ni][3] + b1) * w1;
            }
        }
#pragma unroll
        for (int j = 0; j < 4; j++) {
            p[j] += __shfl_xor_sync(0xffffffffu, p[j], 1);
            p[j] += __shfl_xor_sync(0xffffffffu, p[j], 2);
        }
        if (tig == 0) {
#pragma unroll
            for (int j = 0; j < 4; j++) {
                int rr = wm * 32 + (j >> 1) * 16 + (j & 1) * 8 + g;
                atomicAdd(&sCoef[rr], p[j]);
            }
        }
    }
    __syncthreads();

    // ---- force scatter ----
    if (t < 64) {
        int r = sRow[t];
        float c = sCoef[t];
#pragma unroll
        for (int q = 0; q < 3; q++) {
            float v = sCD[t * 3 + q] * c;
            v = fminf(fmaxf(v, -100.0f), 100.0f);
            atomicAdd(&g_fsum[r * 3 + q], v);
        }
        atomicAdd(&g_cnt[r], 1.0f);
    }
}

// ---------------------------------------------------------------------------
// Node kernel (bf16 3-term, unchanged): h_out = silu(Q1 + agg@Wn1_bot)@Wn2+bn2
// out layout: [vel (N)] [force (N*3)] [h_out (N*128)]
// ---------------------------------------------------------------------------
#define NOFF_X 34816u
#define SMEM_NODE_TOTAL 35840

__global__ __launch_bounds__(256, 3) void node_kernel_mma(
    const float* __restrict__ bn2,
    float* __restrict__ out)
{
    extern __shared__ __align__(16) char smem[];
    unsigned short* sAh = (unsigned short*)smem;
    unsigned short* sAl = (unsigned short*)(smem + 17408);
    float* sBn2 = (float*)(smem + NOFF_X);

    const int t    = threadIdx.x;
    const int lane = t & 31;
    const int wid  = t >> 5;
    const int wm   = wid >> 2;
    const int wn   = wid & 3;
    const int g    = lane >> 2;
    const int tig  = lane & 3;
    const int n0   = blockIdx.x * 64;

    if (t < 128) sBn2[t] = bn2[t];

    for (int i = t; i < 64 * 32; i += 256) {
        int e = i >> 5;
        int k = (i & 31) * 4;
        int n = n0 + e;
        float4 v = make_float4(0.f, 0.f, 0.f, 0.f);
        if (n < NN) v = *(const float4*)(g_agg + (size_t)n * 128 + k);
        uint32_t h0, l0, h1, l1;
        split_pack(v.x, v.y, h0, l0);
        split_pack(v.z, v.w, h1, l1);
        *(uint2*)(sAh + e * SASB + k) = make_uint2(h0, h1);
        *(uint2*)(sAl + e * SASB + k) = make_uint2(l0, l1);
    }
    __syncthreads();

    float acc[2][4][4];

#pragma unroll
    for (int a = 0; a < 2; a++)
#pragma unroll
        for (int b = 0; b < 4; b++)
#pragma unroll
            for (int c = 0; c < 4; c++) acc[a][b][c] = 0.0f;
    gemm_bf16(sAh, sAl, g_Wn1bf, 8, 0, 8, wm, wn, lane, acc);
    __syncthreads();

#pragma unroll
    for (int mi = 0; mi < 2; mi++) {
        int rA = wm * 32 + mi * 16 + g;
        int rB = rA + 8;
        int nA = n0 + rA, nB = n0 + rB;
#pragma unroll
        for (int ni = 0; ni < 4; ni++) {
            int cb = wn * 32 + ni * 8 + tig * 2;
            float q0 = 0.f, q1 = 0.f, q2 = 0.f, q3 = 0.f;
            if (nA < NN) {
                float2 q = *(const float2*)(g_Q1 + (size_t)nA * 128 + cb);
                q0 = q.x; q1 = q.y;
            }
            if (nB < NN) {
                float2 q = *(const float2*)(g_Q1 + (size_t)nB * 128 + cb);
                q2 = q.x; q3 = q.y;
            }
            float x0 = silu_f(acc[mi][ni][0] + q0);
            float x1 = silu_f(acc[mi][ni][1] + q1);
            float x2 = silu_f(acc[mi][ni][2] + q2);
            float x3 = silu_f(acc[mi][ni][3] + q3);
            uint32_t hi, lo;
            split_pack(x0, x1, hi, lo);
            *(uint32_t*)(sAh + rA * SASB + cb) = hi;
            *(uint32_t*)(sAl + rA * SASB + cb) = lo;
            split_pack(x2, x3, hi, lo);
            *(uint32_t*)(sAh + rB * SASB + cb) = hi;
            *(uint32_t*)(sAl + rB * SASB + cb) = lo;
        }
    }
    __syncthreads();

#pragma unroll
    for (int a = 0; a < 2; a++)
#pragma unroll
        for (int b = 0; b < 4; b++)
#pragma unroll
            for (int c = 0; c < 4; c++) acc[a][b][c] = 0.0f;
    gemm_bf16(sAh, sAl, g_Wn2f, 8, 0, 8, wm, wn, lane, acc);

    {
        float* outH = out + (size_t)4 * NN;
#pragma unroll
        for (int mi = 0; mi < 2; mi++) {
            int rA = wm * 32 + mi * 16 + g;
            int rB = rA + 8;
            int nA = n0 + rA, nB = n0 + rB;
#pragma unroll
            for (int ni = 0; ni < 4; ni++) {
                int cb = wn * 32 + ni * 8 + tig * 2;
                float b0 = sBn2[cb], b1 = sBn2[cb + 1];
                if (nA < NN) {
                    float2 v; v.x = acc[mi][ni][0] + b0; v.y = acc[mi][ni][1] + b1;
                    *(float2*)(outH + (size_t)nA * 128 + cb) = v;
                }
                if (nB < NN) {
                    float2 v; v.x = acc[mi][ni][2] + b0; v.y = acc[mi][ni][3] + b1;
                    *(float2*)(outH + (size_t)nB * 128 + cb) = v;
                }
            }
        }
    }

    if (t < 64) {
        int n = n0 + t;
        if (n < NN) {
            float c = g_cnt[n];
            float inv = 1.0f / fmaxf(c, 1.0f);
            out[NN + (size_t)n * 3 + 0] = g_fsum[n * 3 + 0] * inv;
            out[NN + (size_t)n * 3 + 1] = g_fsum[n * 3 + 1] * inv;
            out[NN + (size_t)n * 3 + 2] = g_fsum[n * 3 + 2] * inv;
        }
    }
}

// ---------------------------------------------------------------------------
extern "C" void kernel_launch(void* const* d_in, const int* in_sizes, int n_in,
                              void* d_out, int out_size)
{
    const float* h          = (const float*)d_in[0];
    const float* coord_diff = (const float*)d_in[1];
    const int*   row        = (const int*)  d_in[2];
    const int*   col        = (const int*)  d_in[3];
    const float* We1 = (const float*)d_in[4];
    const float* be1 = (const float*)d_in[5];
    const float* We2 = (const float*)d_in[6];
    const float* be2 = (const float*)d_in[7];
    const float* Wn1 = (const float*)d_in[8];
    const float* bn1 = (const float*)d_in[9];
    const float* Wn2 = (const float*)d_in[10];
    const float* bn2 = (const float*)d_in[11];
    const float* Wc1 = (const float*)d_in[12];
    const float* bc1 = (const float*)d_in[13];
    const float* Wc2 = (const float*)d_in[14];
    const float* Wv1 = (const float*)d_in[15];
    const float* bv1 = (const float*)d_in[16];
    const float* Wv2 = (const float*)d_in[17];
    const float* bv2 = (const float*)d_in[18];
    float* out = (float*)d_out;

    void *aggp, *fsump, *cntp;
    cudaGetSymbolAddress(&aggp, g_agg);
    cudaGetSymbolAddress(&fsump, g_fsum);
    cudaGetSymbolAddress(&cntp, g_cnt);
    cudaMemsetAsync(aggp,  0, (size_t)NN * 128 * sizeof(float));
    cudaMemsetAsync(fsump, 0, (size_t)NN * 3 * sizeof(float));
    cudaMemsetAsync(cntp,  0, (size_t)NN * sizeof(float));

    prep_weights_f<<<320, 256>>>(We1, We2, Wc1, Wn1, Wv1, Wn2);

    cudaFuncSetAttribute(precompute_p, cudaFuncAttributeMaxDynamicSharedMemorySize,
                         SMEM_PRE_TOTAL);
    precompute_p<<<(NN + 63) / 64, 256, SMEM_PRE_TOTAL>>>(h, bn1, bv1, Wv2, bv2, out);

    cudaFuncSetAttribute(edge_kernel_mma, cudaFuncAttributeMaxDynamicSharedMemorySize,
                         SMEM_EDGE_TOTAL);
    edge_kernel_mma<<<EE / 64, 256, SMEM_EDGE_TOTAL>>>(
        coord_diff, row, col, We1, be1, be2, bc1, Wc2);

    cudaFuncSetAttribute(node_kernel_mma, cudaFuncAttributeMaxDynamicSharedMemorySize,
                         SMEM_NODE_TOTAL);
    node_kernel_mma<<<(NN + 63) / 64, 256, SMEM_NODE_TOTAL>>>(bn2, out);
}